// round 13
// baseline (speedup 1.0000x reference)
#include <cuda_runtime.h>
#include <cuda_bf16.h>
#include <math.h>

// ---------------------------------------------------------------------------
// BUTDDecoder: B=128, K=36, V_DIM=2048, EMBED=1024, HID=1024, NTOKEN=10000,
// MAX_LEN=20 (T=19 decode steps).
//
// Round 13: the W2 vocab projection is pipelined INTO the persistent loop:
// step t's idle CTAs (phases 3/5) compute words[t-1] = h2[t] @ W2^T; the
// final timestep runs as a post-loop phase. Host W2 launch removed.
// ---------------------------------------------------------------------------

#define B_     128
#define KOBJ   36
#define VD     2048
#define EMB    1024
#define HID_   1024
#define NTOK   10000
#define MAXLEN 20
#define TT     19
#define H3     3072
#define NCTA   296
#define W2TILES 157          // ceil(10000/64)

typedef unsigned long long ull;
typedef __nv_bfloat16 bf16;

// ------------------------- scratch (device globals) ------------------------
__device__ float g_vs[B_ * KOBJ * VD];
__device__ float g_vmean[B_ * VD];
__device__ float g_vproj[B_ * KOBJ * HID_];
__device__ float g_giv[B_ * H3];
__device__ float g_gip[TT * B_ * H3];
__device__ float g_h1[B_ * HID_];
__device__ float g_h2all[(TT + 1) * B_ * HID_];
__device__ float g_gih[2][B_ * H3];
__device__ float g_gh1[2][B_ * H3];
__device__ float g_gh2[2][B_ * H3];
__device__ float g_qp[2][B_ * HID_];
__device__ float g_gi2h[2][B_ * H3];
__device__ float g_p0[4][B_ * H3];
__device__ float g_Wfq[HID_ * HID_];
__device__ float g_Wf2h[H3 * HID_];
__device__ float g_bfq[HID_];
__device__ float g_bi2f[H3];
__device__ int   g_order[B_];
__device__ int   g_dl[B_];
__device__ float g_mask[TT * B_];
__device__ int          g_barc;
__device__ volatile int g_barg;

// bf16 hi/lo operand arrays (activations)
__device__ bf16 g_vs_h[B_ * KOBJ * VD],        g_vs_l[B_ * KOBJ * VD];
__device__ bf16 g_vm_h[B_ * VD],               g_vm_l[B_ * VD];
__device__ bf16 g_x1p_h[TT * B_ * EMB],        g_x1p_l[TT * B_ * EMB];
__device__ bf16 g_h1_h[B_ * HID_],             g_h1_l[B_ * HID_];
__device__ bf16 g_h2_h[(TT + 1) * B_ * HID_],  g_h2_l[(TT + 1) * B_ * HID_];
__device__ bf16 g_attv_h[B_ * VD],             g_attv_l[B_ * VD];

// bf16 hi/lo weight arrays
__device__ bf16 g_wih1h_h[H3 * HID_],  g_wih1h_l[H3 * HID_];   // Wih1[:, :1024]
__device__ bf16 g_w1v_h[H3 * VD],      g_w1v_l[H3 * VD];       // Wih1[:, 1024:3072]
__device__ bf16 g_w1p_h[H3 * EMB],     g_w1p_l[H3 * EMB];      // Wih1[:, 3072:4096]
__device__ bf16 g_whh1_h[H3 * HID_],   g_whh1_l[H3 * HID_];
__device__ bf16 g_whh2_h[H3 * HID_],   g_whh2_l[H3 * HID_];
__device__ bf16 g_wv_h[HID_ * VD],     g_wv_l[HID_ * VD];
__device__ bf16 g_wih2v_h[H3 * VD],    g_wih2v_l[H3 * VD];     // Wih2[:, :2048]
__device__ bf16 g_wih2x_h[H3 * HID_],  g_wih2x_l[H3 * HID_];   // Wih2[:, 2048:]
__device__ bf16 g_w2_h[NTOK * HID_],   g_w2_l[NTOK * HID_];
__device__ bf16 g_wq_h[HID_ * HID_],   g_wq_l[HID_ * HID_];
__device__ bf16 g_w1t_h[HID_ * HID_],  g_w1t_l[HID_ * HID_];
__device__ bf16 g_wfq_h[HID_ * HID_],  g_wfq_l[HID_ * HID_];
__device__ bf16 g_wf2h_h[H3 * HID_],   g_wf2h_l[H3 * HID_];

// --------------------------- small helpers ---------------------------------
__device__ __forceinline__ void split2(float x, bf16& h, bf16& l) {
    h = __float2bfloat16(x);
    l = __float2bfloat16(x - __bfloat162float(h));
}
__device__ __forceinline__ unsigned smem_u32(const void* p) {
    return (unsigned)__cvta_generic_to_shared(p);
}
__device__ __forceinline__ void cpa16(unsigned dst, const void* src, int sz) {
    asm volatile("cp.async.ca.shared.global [%0], [%1], 16, %2;"
                 :: "r"(dst), "l"(src), "r"(sz));
}

#define LDM_X4(r0, r1, r2, r3, addr) \
    asm volatile("ldmatrix.sync.aligned.m8n8.x4.shared.b16 {%0,%1,%2,%3}, [%4];" \
        : "=r"(r0), "=r"(r1), "=r"(r2), "=r"(r3) : "r"(addr))

#define MMA16816(c, a, b) \
    asm volatile("mma.sync.aligned.m16n8k16.row.col.f32.bf16.bf16.f32 " \
        "{%0,%1,%2,%3}, {%4,%5,%6,%7}, {%8,%9}, {%0,%1,%2,%3};" \
        : "+f"((c)[0]), "+f"((c)[1]), "+f"((c)[2]), "+f"((c)[3]) \
        : "r"((a)[0]), "r"((a)[1]), "r"((a)[2]), "r"((a)[3]), \
          "r"((b)[0]), "r"((b)[1]))

// ----------------- host-launched tensor GEMM (big GEMMs) -------------------
struct TZ {
    const bf16 *Ahi, *Alo, *Whi, *Wlo;
    float* C; const float* bias;
    int lda, ldw, ldc, M, N, K, mode;
};
struct TP { TZ z[2]; const float* mask; };

template<int BN> struct TGC {
    static constexpr int BUF   = 32768 + BN * 256;
    static constexpr int SMEM  = 2 * BUF + 1024;
    static constexpr int THR   = BN * 2;
    static constexpr int WN    = BN / 32;
    static constexpr int RPI   = BN / 4;
    static constexpr int AIT   = 128 / RPI;
};

template<int BN>
__global__ void __launch_bounds__(TGC<BN>::THR) tgemm_k(TP p)
{
    const TZ gz = p.z[blockIdx.z];
    const int bn0 = blockIdx.x * BN;  if (bn0 >= gz.N) return;
    const int bm0 = blockIdx.y * 128; if (bm0 >= gz.M) return;
    const int tid = threadIdx.x, wid = tid >> 5, lane = tid & 31;
    const int wm = wid / TGC<BN>::WN, wn = wid % TGC<BN>::WN;

    extern __shared__ char dsm[];
    unsigned dbase = smem_u32(dsm);
    unsigned s0 = (dbase + 1023u) & ~1023u;
    unsigned sAh[2], sAl[2], sBh[2], sBl[2];
#pragma unroll
    for (int b = 0; b < 2; b++) {
        sAh[b] = s0 + b * TGC<BN>::BUF;
        sAl[b] = sAh[b] + 16384;
        sBh[b] = sAl[b] + 16384;
        sBl[b] = sBh[b] + BN * 128;
    }

    const int lrow = tid >> 3;
    const int lch  = tid & 7;
    auto load_chunk = [&](int c, int buf) {
        const int c0 = c * 64;
#pragma unroll
        for (int i = 0; i < TGC<BN>::AIT; i++) {
            int row = i * TGC<BN>::RPI + lrow;
            unsigned off = (unsigned)(row * 128) + (unsigned)(((lch ^ (row & 7)) * 16));
            cpa16(sAh[buf] + off, gz.Ahi + (size_t)(bm0 + row) * gz.lda + c0 + lch * 8, 16);
            cpa16(sAl[buf] + off, gz.Alo + (size_t)(bm0 + row) * gz.lda + c0 + lch * 8, 16);
        }
#pragma unroll
        for (int i = 0; i < 4; i++) {
            int row = i * TGC<BN>::RPI + lrow;
            unsigned off = (unsigned)(row * 128) + (unsigned)(((lch ^ (row & 7)) * 16));
            int n = bn0 + row;
            int sz = (n < gz.N) ? 16 : 0;
            int nn = (n < gz.N) ? n : 0;
            cpa16(sBh[buf] + off, gz.Whi + (size_t)nn * gz.ldw + c0 + lch * 8, sz);
            cpa16(sBl[buf] + off, gz.Wlo + (size_t)nn * gz.ldw + c0 + lch * 8, sz);
        }
        asm volatile("cp.async.commit_group;");
    };

    float acc[4][4][4];
#pragma unroll
    for (int mi = 0; mi < 4; mi++)
#pragma unroll
        for (int nj = 0; nj < 4; nj++)
#pragma unroll
            for (int e = 0; e < 4; e++) acc[mi][nj][e] = 0.f;

    const int xorkey = lane & 7;
    const int nch = gz.K / 64;
    load_chunk(0, 0);

    for (int c = 0; c < nch; c++) {
        if (c + 1 < nch) {
            load_chunk(c + 1, (c + 1) & 1);
            asm volatile("cp.async.wait_group 1;");
        } else {
            asm volatile("cp.async.wait_group 0;");
        }
        __syncthreads();
        const unsigned tAh = sAh[c & 1], tAl = sAl[c & 1];
        const unsigned tBh = sBh[c & 1], tBl = sBl[c & 1];
#pragma unroll
        for (int ks = 0; ks < 4; ks++) {
            unsigned Ah[4][4], Al[4][4];
            {
                const int arow = wm * 64 + (lane & 15);
                const unsigned aoff =
                    (unsigned)((((2 * ks) + (lane >> 4)) ^ xorkey) * 16);
#pragma unroll
                for (int mi = 0; mi < 4; mi++) {
                    unsigned ad = (unsigned)((arow + mi * 16) * 128) + aoff;
                    LDM_X4(Ah[mi][0], Ah[mi][1], Ah[mi][2], Ah[mi][3], tAh + ad);
                    LDM_X4(Al[mi][0], Al[mi][1], Al[mi][2], Al[mi][3], tAl + ad);
                }
            }
            unsigned Bh[4][2], Bl[4][2];
            {
                const int brow = wn * 32 + (lane & 7) + ((lane >> 4) << 3);
                const unsigned boff =
                    (unsigned)((((2 * ks) + ((lane >> 3) & 1)) ^ xorkey) * 16);
                unsigned r0, r1, r2, r3;
                unsigned b0 = (unsigned)(brow * 128) + boff;
                LDM_X4(r0, r1, r2, r3, tBh + b0);
                Bh[0][0] = r0; Bh[0][1] = r1; Bh[1][0] = r2; Bh[1][1] = r3;
                LDM_X4(r0, r1, r2, r3, tBh + b0 + 16 * 128);
                Bh[2][0] = r0; Bh[2][1] = r1; Bh[3][0] = r2; Bh[3][1] = r3;
                LDM_X4(r0, r1, r2, r3, tBl + b0);
                Bl[0][0] = r0; Bl[0][1] = r1; Bl[1][0] = r2; Bl[1][1] = r3;
                LDM_X4(r0, r1, r2, r3, tBl + b0 + 16 * 128);
                Bl[2][0] = r0; Bl[2][1] = r1; Bl[3][0] = r2; Bl[3][1] = r3;
            }
#pragma unroll
            for (int mi = 0; mi < 4; mi++)
#pragma unroll
                for (int nj = 0; nj < 4; nj++) {
                    MMA16816(acc[mi][nj], Ah[mi], Bh[nj]);
                    MMA16816(acc[mi][nj], Ah[mi], Bl[nj]);
                    MMA16816(acc[mi][nj], Al[mi], Bh[nj]);
                }
        }
        __syncthreads();
    }

    const int g = lane >> 2, tig = lane & 3;
    auto stc = [&](int m, int n, float val) {
        if (n >= gz.N) return;
        if (gz.bias) val += gz.bias[n];
        if (gz.mode == 1) val = fmaxf(val, 0.f);
        gz.C[(size_t)m * gz.ldc + n] = val;
    };
#pragma unroll
    for (int mi = 0; mi < 4; mi++)
#pragma unroll
        for (int nj = 0; nj < 4; nj++) {
            int row = bm0 + wm * 64 + mi * 16 + g;
            int col = bn0 + wn * 32 + nj * 8 + 2 * tig;
            stc(row,     col,     acc[mi][nj][0]);
            stc(row,     col + 1, acc[mi][nj][1]);
            stc(row + 8, col,     acc[mi][nj][2]);
            stc(row + 8, col + 1, acc[mi][nj][3]);
        }
}

// ------------------ persistent-loop device machinery ------------------------
__device__ __forceinline__ void grid_bar()
{
    __syncthreads();
    if (threadIdx.x == 0) {
        int gen = g_barg;
        __threadfence();
        if (atomicAdd(&g_barc, 1) == NCTA - 1) {
            g_barc = 0;
            __threadfence();
            g_barg = gen + 1;
        } else {
            while (g_barg == gen) __nanosleep(32);
            __threadfence();
        }
    }
    __syncthreads();
}

// one 128x64xK GEMM tile, 256 threads (8 warps: 4m x 2n), single-buffered.
__device__ __noinline__ void gemm_task(
    const bf16* __restrict__ Ah0, const bf16* __restrict__ Al0, int lda,
    const bf16* __restrict__ Wh0, const bf16* __restrict__ Wl0, int ldw,
    float* __restrict__ C, int ldc, int bn0, int Ksz,
    const float* __restrict__ bias, char* dsm)
{
    const int tid = threadIdx.x, wid = tid >> 5, lane = tid & 31;
    const int wm = wid >> 1, wn = wid & 1;

    unsigned dbase = smem_u32(dsm);
    unsigned s0 = (dbase + 1023u) & ~1023u;
    const unsigned sAh = s0;
    const unsigned sAl = sAh + 16384;
    const unsigned sBh = sAl + 16384;
    const unsigned sBl = sBh + 8192;

    const int lrow = tid >> 3;
    const int lch  = tid & 7;
    const bf16* Wb_h = Wh0 + (size_t)bn0 * ldw;
    const bf16* Wb_l = Wl0 + (size_t)bn0 * ldw;

    float acc[2][4][4];
#pragma unroll
    for (int mi = 0; mi < 2; mi++)
#pragma unroll
        for (int nj = 0; nj < 4; nj++)
#pragma unroll
            for (int e = 0; e < 4; e++) acc[mi][nj][e] = 0.f;

    const int xorkey = lane & 7;
    const int nch = Ksz / 64;

    for (int c = 0; c < nch; c++) {
        const int c0 = c * 64;
#pragma unroll
        for (int i = 0; i < 4; i++) {
            int row = i * 32 + lrow;
            unsigned off = (unsigned)(row * 128) + (unsigned)(((lch ^ (row & 7)) * 16));
            cpa16(sAh + off, Ah0 + (size_t)row * lda + c0 + lch * 8, 16);
            cpa16(sAl + off, Al0 + (size_t)row * lda + c0 + lch * 8, 16);
        }
#pragma unroll
        for (int i = 0; i < 2; i++) {
            int row = i * 32 + lrow;
            unsigned off = (unsigned)(row * 128) + (unsigned)(((lch ^ (row & 7)) * 16));
            cpa16(sBh + off, Wb_h + (size_t)row * ldw + c0 + lch * 8, 16);
            cpa16(sBl + off, Wb_l + (size_t)row * ldw + c0 + lch * 8, 16);
        }
        asm volatile("cp.async.commit_group;");
        asm volatile("cp.async.wait_group 0;");
        __syncthreads();

#pragma unroll
        for (int ks = 0; ks < 4; ks++) {
            unsigned Ahf[2][4], Alf[2][4];
            {
                const int arow = wm * 32 + (lane & 15);
                const unsigned aoff =
                    (unsigned)((((2 * ks) + (lane >> 4)) ^ xorkey) * 16);
#pragma unroll
                for (int mi = 0; mi < 2; mi++) {
                    unsigned ad = (unsigned)((arow + mi * 16) * 128) + aoff;
                    LDM_X4(Ahf[mi][0], Ahf[mi][1], Ahf[mi][2], Ahf[mi][3], sAh + ad);
                    LDM_X4(Alf[mi][0], Alf[mi][1], Alf[mi][2], Alf[mi][3], sAl + ad);
                }
            }
            unsigned Bh[4][2], Bl[4][2];
            {
                const int brow = wn * 32 + (lane & 7) + ((lane >> 4) << 3);
                const unsigned boff =
                    (unsigned)((((2 * ks) + ((lane >> 3) & 1)) ^ xorkey) * 16);
                unsigned r0, r1, r2, r3;
                unsigned b0 = (unsigned)(brow * 128) + boff;
                LDM_X4(r0, r1, r2, r3, sBh + b0);
                Bh[0][0] = r0; Bh[0][1] = r1; Bh[1][0] = r2; Bh[1][1] = r3;
                LDM_X4(r0, r1, r2, r3, sBh + b0 + 16 * 128);
                Bh[2][0] = r0; Bh[2][1] = r1; Bh[3][0] = r2; Bh[3][1] = r3;
                LDM_X4(r0, r1, r2, r3, sBl + b0);
                Bl[0][0] = r0; Bl[0][1] = r1; Bl[1][0] = r2; Bl[1][1] = r3;
                LDM_X4(r0, r1, r2, r3, sBl + b0 + 16 * 128);
                Bl[2][0] = r0; Bl[2][1] = r1; Bl[3][0] = r2; Bl[3][1] = r3;
            }
#pragma unroll
            for (int mi = 0; mi < 2; mi++)
#pragma unroll
                for (int nj = 0; nj < 4; nj++) {
                    MMA16816(acc[mi][nj], Ahf[mi], Bh[nj]);
                    MMA16816(acc[mi][nj], Ahf[mi], Bl[nj]);
                    MMA16816(acc[mi][nj], Alf[mi], Bh[nj]);
                }
        }
        __syncthreads();
    }

    const int g = lane >> 2, tig = lane & 3;
#pragma unroll
    for (int mi = 0; mi < 2; mi++)
#pragma unroll
        for (int nj = 0; nj < 4; nj++) {
            int row = wm * 32 + mi * 16 + g;
            int col = bn0 + wn * 32 + nj * 8 + 2 * tig;
            float v0 = acc[mi][nj][0], v1 = acc[mi][nj][1];
            float v2 = acc[mi][nj][2], v3 = acc[mi][nj][3];
            if (bias) {
                v0 += bias[col]; v1 += bias[col + 1];
                v2 += bias[col]; v3 += bias[col + 1];
            }
            C[(size_t)row * ldc + col]           = v0;
            C[(size_t)row * ldc + col + 1]       = v1;
            C[(size_t)(row + 8) * ldc + col]     = v2;
            C[(size_t)(row + 8) * ldc + col + 1] = v3;
        }
}

// W2 tile: words[ts] rows (all 128 b) x cols [bn0, bn0+64), K=1024.
// predict[(b*MAXLEN+ts)*NTOK + n] = (h2[ts+1][b,:]@W2[n,:] + b2[n]) * mask[ts*B+b]
__device__ __noinline__ void gemm_task_w2(
    int ts, int bn0, const float* __restrict__ b2,
    float* __restrict__ predict, char* dsm)
{
    const bf16* Ah0 = g_h2_h + (size_t)(ts + 1) * B_ * HID_;
    const bf16* Al0 = g_h2_l + (size_t)(ts + 1) * B_ * HID_;
    const int tid = threadIdx.x, wid = tid >> 5, lane = tid & 31;
    const int wm = wid >> 1, wn = wid & 1;

    unsigned dbase = smem_u32(dsm);
    unsigned s0 = (dbase + 1023u) & ~1023u;
    const unsigned sAh = s0;
    const unsigned sAl = sAh + 16384;
    const unsigned sBh = sAl + 16384;
    const unsigned sBl = sBh + 8192;

    const int lrow = tid >> 3;
    const int lch  = tid & 7;

    float acc[2][4][4];
#pragma unroll
    for (int mi = 0; mi < 2; mi++)
#pragma unroll
        for (int nj = 0; nj < 4; nj++)
#pragma unroll
            for (int e = 0; e < 4; e++) acc[mi][nj][e] = 0.f;

    const int xorkey = lane & 7;

    for (int c = 0; c < 16; c++) {          // K = 1024
        const int c0 = c * 64;
#pragma unroll
        for (int i = 0; i < 4; i++) {
            int row = i * 32 + lrow;
            unsigned off = (unsigned)(row * 128) + (unsigned)(((lch ^ (row & 7)) * 16));
            cpa16(sAh + off, Ah0 + (size_t)row * HID_ + c0 + lch * 8, 16);
            cpa16(sAl + off, Al0 + (size_t)row * HID_ + c0 + lch * 8, 16);
        }
#pragma unroll
        for (int i = 0; i < 2; i++) {
            int row = i * 32 + lrow;
            unsigned off = (unsigned)(row * 128) + (unsigned)(((lch ^ (row & 7)) * 16));
            int n = bn0 + row;
            int sz = (n < NTOK) ? 16 : 0;
            int nn = (n < NTOK) ? n : 0;
            cpa16(sBh + off, g_w2_h + (size_t)nn * HID_ + c0 + lch * 8, sz);
            cpa16(sBl + off, g_w2_l + (size_t)nn * HID_ + c0 + lch * 8, sz);
        }
        asm volatile("cp.async.commit_group;");
        asm volatile("cp.async.wait_group 0;");
        __syncthreads();

#pragma unroll
        for (int ks = 0; ks < 4; ks++) {
            unsigned Ahf[2][4], Alf[2][4];
            {
                const int arow = wm * 32 + (lane & 15);
                const unsigned aoff =
                    (unsigned)((((2 * ks) + (lane >> 4)) ^ xorkey) * 16);
#pragma unroll
                for (int mi = 0; mi < 2; mi++) {
                    unsigned ad = (unsigned)((arow + mi * 16) * 128) + aoff;
                    LDM_X4(Ahf[mi][0], Ahf[mi][1], Ahf[mi][2], Ahf[mi][3], sAh + ad);
                    LDM_X4(Alf[mi][0], Alf[mi][1], Alf[mi][2], Alf[mi][3], sAl + ad);
                }
            }
            unsigned Bh[4][2], Bl[4][2];
            {
                const int brow = wn * 32 + (lane & 7) + ((lane >> 4) << 3);
                const unsigned boff =
                    (unsigned)((((2 * ks) + ((lane >> 3) & 1)) ^ xorkey) * 16);
                unsigned r0, r1, r2, r3;
                unsigned b0 = (unsigned)(brow * 128) + boff;
                LDM_X4(r0, r1, r2, r3, sBh + b0);
                Bh[0][0] = r0; Bh[0][1] = r1; Bh[1][0] = r2; Bh[1][1] = r3;
                LDM_X4(r0, r1, r2, r3, sBh + b0 + 16 * 128);
                Bh[2][0] = r0; Bh[2][1] = r1; Bh[3][0] = r2; Bh[3][1] = r3;
                LDM_X4(r0, r1, r2, r3, sBl + b0);
                Bl[0][0] = r0; Bl[0][1] = r1; Bl[1][0] = r2; Bl[1][1] = r3;
                LDM_X4(r0, r1, r2, r3, sBl + b0 + 16 * 128);
                Bl[2][0] = r0; Bl[2][1] = r1; Bl[3][0] = r2; Bl[3][1] = r3;
            }
#pragma unroll
            for (int mi = 0; mi < 2; mi++)
#pragma unroll
                for (int nj = 0; nj < 4; nj++) {
                    MMA16816(acc[mi][nj], Ahf[mi], Bh[nj]);
                    MMA16816(acc[mi][nj], Ahf[mi], Bl[nj]);
                    MMA16816(acc[mi][nj], Alf[mi], Bh[nj]);
                }
        }
        __syncthreads();
    }

    const int g = lane >> 2, tig = lane & 3;
#pragma unroll
    for (int mi = 0; mi < 2; mi++)
#pragma unroll
        for (int nj = 0; nj < 4; nj++) {
            int b0r = wm * 32 + mi * 16 + g;       // batch row
            int col = bn0 + wn * 32 + nj * 8 + 2 * tig;
#pragma unroll
            for (int half = 0; half < 2; half++) {
                int b = b0r + half * 8;
                float m = g_mask[ts * B_ + b];
                size_t orow = ((size_t)b * MAXLEN + ts) * NTOK;
                float v0 = acc[mi][nj][half * 2 + 0];
                float v1 = acc[mi][nj][half * 2 + 1];
                if (col < NTOK)     predict[orow + col]     = (v0 + b2[col]) * m;
                if (col + 1 < NTOK) predict[orow + col + 1] = (v1 + b2[col + 1]) * m;
            }
        }
}

// ------------------------- persistent loop kernel ---------------------------
__global__ void __launch_bounds__(256, 2) loop_kernel(
    const float* __restrict__ bhh1, const float* __restrict__ bhh2,
    const float* __restrict__ wa,   const float* __restrict__ ba,
    const float* __restrict__ b2,
    float* __restrict__ alphas, float* __restrict__ predict)
{
    extern __shared__ char dsm[];
    const int cta = blockIdx.x;
    const int tid = threadIdx.x;

    for (int t = 0; t < TT; t++) {
        const bf16*  h2ph = g_h2_h + (size_t)t * B_ * HID_;
        const bf16*  h2pl = g_h2_l + (size_t)t * B_ * HID_;
        const float* h2prev = g_h2all + (size_t)t * B_ * HID_;
        float*       h2next = g_h2all + (size_t)(t + 1) * B_ * HID_;

        // ---- phase 1: stage1 (gih, gh1, gh2), 288 tasks ----
        for (int task = cta; task < 288; task += NCTA) {
            int s = task & 1, x = (task >> 1) % 48, o = task / 96;
            int ko = s * 512;
            if (o == 0)
                gemm_task(h2ph + ko, h2pl + ko, HID_,
                          g_wih1h_h + ko, g_wih1h_l + ko, HID_,
                          g_gih[s], H3, x * 64, 512, nullptr, dsm);
            else if (o == 1)
                gemm_task(g_h1_h + ko, g_h1_l + ko, HID_,
                          g_whh1_h + ko, g_whh1_l + ko, HID_,
                          g_gh1[s], H3, x * 64, 512, s == 0 ? bhh1 : nullptr, dsm);
            else
                gemm_task(h2ph + ko, h2pl + ko, HID_,
                          g_whh2_h + ko, g_whh2_l + ko, HID_,
                          g_gh2[s], H3, x * 64, 512, s == 0 ? bhh2 : nullptr, dsm);
        }
        grid_bar();

        // ---- phase 2: GRU1 pointwise ----
        {
            const float* gip = g_gip + (size_t)t * B_ * H3;
            for (int idx = cta * 256 + tid; idx < B_ * HID_; idx += NCTA * 256) {
                int b = idx >> 10, j = idx & 1023;
                size_t base = (size_t)b * H3 + j;
                float gr = g_giv[base] + gip[base] + g_gih[0][base] + g_gih[1][base];
                float gz = g_giv[base + HID_] + gip[base + HID_]
                         + g_gih[0][base + HID_] + g_gih[1][base + HID_];
                float gn = g_giv[base + 2*HID_] + gip[base + 2*HID_]
                         + g_gih[0][base + 2*HID_] + g_gih[1][base + 2*HID_];
                float ghr = g_gh1[0][base] + g_gh1[1][base];
                float ghz = g_gh1[0][base + HID_] + g_gh1[1][base + HID_];
                float ghn = g_gh1[0][base + 2*HID_] + g_gh1[1][base + 2*HID_];
                float r = 1.f / (1.f + expf(-(gr + ghr)));
                float z = 1.f / (1.f + expf(-(gz + ghz)));
                float n = tanhf(gn + r * ghn);
                float h = (1.f - z) * n + z * g_h1[idx];
                g_h1[idx] = h;
                split2(h, g_h1_h[idx], g_h1_l[idx]);
            }
        }
        grid_bar();

        // ---- phase 3: stage2 (128 tasks) + pipelined W2 tiles 0..99 ----
        if (cta < 128) {
            int task = cta;
            if (task < 32) {
                int s = task & 1, x = (task >> 1);
                int ko = s * 512;
                gemm_task(g_h1_h + ko, g_h1_l + ko, HID_,
                          g_wfq_h + ko, g_wfq_l + ko, HID_,
                          g_qp[s], HID_, x * 64, 512, nullptr, dsm);
            } else {
                int u = task - 32;
                int s = u & 1, x = (u >> 1);
                int ko = s * 512;
                gemm_task(g_h1_h + ko, g_h1_l + ko, HID_,
                          g_wf2h_h + ko, g_wf2h_l + ko, HID_,
                          g_gi2h[s], H3, x * 64, 512, nullptr, dsm);
            }
        } else if (t > 0 && cta - 128 < 100) {
            gemm_task_w2(t - 1, (cta - 128) * 64, b2, predict, dsm);
        }
        grid_bar();

        // ---- phase 4: attention, one batch row per CTA ----
        if (cta < B_) {
            int b = cta;
            float* qs  = (float*)dsm;
            float* att = qs + HID_;
            for (int d = tid; d < HID_; d += 256) {
                float qv = g_qp[0][b * HID_ + d] + g_qp[1][b * HID_ + d] + g_bfq[d];
                qs[d] = fmaxf(qv, 0.f) * wa[d];
            }
            __syncthreads();
            int warp = tid >> 5, lane = tid & 31;
            for (int k = warp; k < KOBJ; k += 8) {
                const float* vp = g_vproj + ((size_t)b * KOBJ + k) * HID_;
                float s = 0.f;
                for (int d = lane; d < HID_; d += 32) s += vp[d] * qs[d];
#pragma unroll
                for (int o = 16; o; o >>= 1) s += __shfl_down_sync(0xffffffffu, s, o);
                if (lane == 0) att[k] = s + ba[0];
            }
            __syncthreads();
            if (tid == 0) {
                float mx = att[0];
                for (int k = 1; k < KOBJ; k++) mx = fmaxf(mx, att[k]);
                float ssum = 0.f;
                for (int k = 0; k < KOBJ; k++) { float e = expf(att[k] - mx); att[k] = e; ssum += e; }
                float inv = 1.f / ssum;
                for (int k = 0; k < KOBJ; k++) att[k] *= inv;
            }
            __syncthreads();
            if (tid < KOBJ) {
                float m = (t < g_dl[b]) ? 1.f : 0.f;
                alphas[((size_t)b * MAXLEN + t) * KOBJ + tid] = att[tid] * m;
            }
            for (int d = tid; d < VD; d += 256) {
                const float* vb = g_vs + (size_t)b * KOBJ * VD + d;
                float s = 0.f;
#pragma unroll 6
                for (int k = 0; k < KOBJ; k++) s += att[k] * vb[(size_t)k * VD];
                split2(s, g_attv_h[b * VD + d], g_attv_l[b * VD + d]);
            }
        }
        grid_bar();

        // ---- phase 5: gi2att (192 tasks) + pipelined W2 tiles 100..156 ----
        if (cta < 192) {
            int task = cta;
            int s = task & 3, x = task >> 2;
            int ko = s * 512;
            gemm_task(g_attv_h + ko, g_attv_l + ko, VD,
                      g_wih2v_h + ko, g_wih2v_l + ko, VD,
                      g_p0[s], H3, x * 64, 512, nullptr, dsm);
        } else if (t > 0 && cta - 192 < 57) {
            gemm_task_w2(t - 1, (100 + (cta - 192)) * 64, b2, predict, dsm);
        }
        grid_bar();

        // ---- phase 6: GRU2 pointwise ----
        {
            bf16* hh = g_h2_h + (size_t)(t + 1) * B_ * HID_;
            bf16* hl = g_h2_l + (size_t)(t + 1) * B_ * HID_;
            for (int idx = cta * 256 + tid; idx < B_ * HID_; idx += NCTA * 256) {
                int b = idx >> 10, j = idx & 1023;
                size_t base = (size_t)b * H3 + j;
                float gr = g_bi2f[j], gz = g_bi2f[j + HID_], gn = g_bi2f[j + 2*HID_];
#pragma unroll
                for (int s = 0; s < 4; s++) {
                    gr += g_p0[s][base]; gz += g_p0[s][base + HID_]; gn += g_p0[s][base + 2*HID_];
                }
#pragma unroll
                for (int s = 0; s < 2; s++) {
                    gr += g_gi2h[s][base]; gz += g_gi2h[s][base + HID_]; gn += g_gi2h[s][base + 2*HID_];
                }
                float ghr = g_gh2[0][base] + g_gh2[1][base];
                float ghz = g_gh2[0][base + HID_] + g_gh2[1][base + HID_];
                float ghn = g_gh2[0][base + 2*HID_] + g_gh2[1][base + 2*HID_];
                float r = 1.f / (1.f + expf(-(gr + ghr)));
                float z = 1.f / (1.f + expf(-(gz + ghz)));
                float n = tanhf(gn + r * ghn);
                float h = (1.f - z) * n + z * h2prev[idx];
                h2next[idx] = h;
                split2(h, hh[idx], hl[idx]);
            }
        }
        grid_bar();
    }

    // ---- post-loop: final timestep's W2 (157 tasks, one round) ----
    for (int task = cta; task < W2TILES; task += NCTA)
        gemm_task_w2(TT - 1, task * 64, b2, predict, dsm);
}

// ------------------------------- small kernels -----------------------------
__global__ void meta_kernel(const int* __restrict__ cap_len)
{
    int i = threadIdx.x;
    int ci = cap_len[i];
    int rank = 0;
    for (int j = 0; j < B_; j++) {
        int cj = cap_len[j];
        if (cj > ci || (cj == ci && j < i)) rank++;
    }
    g_order[rank] = i;
    __syncthreads();
    g_dl[i] = cap_len[g_order[i]] - 1;
    __syncthreads();
    int dli = g_dl[i];
    for (int t = 0; t < TT; t++) g_mask[t * B_ + i] = (t < dli) ? 1.f : 0.f;
    if (i == 0) { g_barc = 0; g_barg = 0; }
}

__global__ void zero_init_kernel()
{
    int idx = blockIdx.x * 256 + threadIdx.x;
    if (idx < B_ * HID_) {
        g_h1[idx] = 0.f;    g_h1_h[idx] = __float2bfloat16(0.f); g_h1_l[idx] = __float2bfloat16(0.f);
        g_h2all[idx] = 0.f; g_h2_h[idx] = __float2bfloat16(0.f); g_h2_l[idx] = __float2bfloat16(0.f);
    }
}

__global__ void permute_v_kernel(const float* __restrict__ v)
{
    size_t idx = (size_t)blockIdx.x * 256 + threadIdx.x;
    if (idx >= (size_t)B_ * KOBJ * VD) return;
    int b = (int)(idx / ((size_t)KOBJ * VD));
    size_t rest = idx % ((size_t)KOBJ * VD);
    float x = v[(size_t)g_order[b] * KOBJ * VD + rest];
    g_vs[idx] = x;
    split2(x, g_vs_h[idx], g_vs_l[idx]);
}

__global__ void vmean_kernel()
{
    int idx = blockIdx.x * 256 + threadIdx.x;
    if (idx >= B_ * VD) return;
    int b = idx / VD, d = idx % VD;
    const float* p = g_vs + (size_t)b * KOBJ * VD + d;
    float s = 0.f;
#pragma unroll 6
    for (int k = 0; k < KOBJ; k++) s += p[(size_t)k * VD];
    s *= (1.f / (float)KOBJ);
    g_vmean[idx] = s;
    split2(s, g_vm_h[idx], g_vm_l[idx]);
}

__global__ void build_x1p_kernel(const float* __restrict__ caption)
{
    size_t idx = (size_t)blockIdx.x * 256 + threadIdx.x;
    if (idx >= (size_t)TT * B_ * EMB) return;
    int c = (int)(idx % EMB);
    int r = (int)(idx / EMB);
    int t = r / B_, b = r % B_;
    float val = caption[((size_t)g_order[b] * MAXLEN + t) * EMB + c];
    split2(val, g_x1p_h[idx], g_x1p_l[idx]);
}

__global__ void convw_kernel(const float* __restrict__ src, int ld, int col0,
                             int rows, int cols, bf16* __restrict__ hi,
                             bf16* __restrict__ lo)
{
    size_t idx = (size_t)blockIdx.x * 256 + threadIdx.x;
    if (idx >= (size_t)rows * cols) return;
    int r = (int)(idx / cols), c = (int)(idx % cols);
    split2(src[(size_t)r * ld + col0 + c], hi[idx], lo[idx]);
}

__global__ void tsplit_kernel(const float* __restrict__ src,
                              bf16* __restrict__ hi, bf16* __restrict__ lo)
{
    __shared__ float tile[32][33];
    int bx = blockIdx.x * 32, by = blockIdx.y * 32;
#pragma unroll
    for (int i = 0; i < 32; i += 8)
        tile[threadIdx.y + i][threadIdx.x] =
            src[(size_t)(by + threadIdx.y + i) * HID_ + bx + threadIdx.x];
    __syncthreads();
#pragma unroll
    for (int i = 0; i < 32; i += 8) {
        float vv = tile[threadIdx.x][threadIdx.y + i];
        size_t o = (size_t)(bx + threadIdx.y + i) * HID_ + by + threadIdx.x;
        split2(vv, hi[o], lo[o]);
    }
}

__global__ void fusebias_kernel(const float* __restrict__ Wq,
                                const float* __restrict__ bq,
                                const float* __restrict__ b1,
                                const float* __restrict__ Wih2,
                                const float* __restrict__ bih2)
{
    int idx = blockIdx.x * 256 + threadIdx.x;
    if (idx < HID_) {
        const float* w = Wq + (size_t)idx * HID_;
        float s = 0.f;
        for (int j = 0; j < HID_; j++) s += w[j] * b1[j];
        g_bfq[idx] = s + bq[idx];
    } else if (idx < HID_ + H3) {
        int n = idx - HID_;
        const float* w = Wih2 + (size_t)n * H3 + VD;
        float s = 0.f;
        for (int j = 0; j < HID_; j++) s += w[j] * b1[j];
        g_bi2f[n] = s + bih2[n];
    }
}

__global__ void zero_tails_kernel(float* __restrict__ predict,
                                  float* __restrict__ alphas)
{
    int idx = blockIdx.x * 256 + threadIdx.x;
    if (idx < B_ * NTOK) {
        int b = idx / NTOK, n = idx % NTOK;
        predict[((size_t)b * MAXLEN + (MAXLEN - 1)) * NTOK + n] = 0.f;
    } else if (idx < B_ * NTOK + B_ * KOBJ) {
        int r = idx - B_ * NTOK;
        int b = r / KOBJ, k = r % KOBJ;
        alphas[((size_t)b * MAXLEN + (MAXLEN - 1)) * KOBJ + k] = 0.f;
    }
}

// --------------------------------- launch ----------------------------------
static inline TZ mkt(const bf16* Ah, const bf16* Al, int lda,
                     const bf16* Wh, const bf16* Wl, int ldw,
                     float* C, int ldc, int M, int N, int K,
                     const float* bias, int mode)
{
    TZ z; z.Ahi = Ah; z.Alo = Al; z.Whi = Wh; z.Wlo = Wl;
    z.C = C; z.bias = bias; z.lda = lda; z.ldw = ldw; z.ldc = ldc;
    z.M = M; z.N = N; z.K = K; z.mode = mode;
    return z;
}

#define SYMADDR(var, sym) cudaGetSymbolAddress((void**)&var, sym)

extern "C" void kernel_launch(void* const* d_in, const int* in_sizes, int n_in,
                              void* d_out, int out_size)
{
    const float* v       = (const float*)d_in[0];
    const float* caption = (const float*)d_in[1];
    const int*   cap_len = (const int*)  d_in[2];
    const float* Wih1    = (const float*)d_in[3];
    const float* Whh1    = (const float*)d_in[4];
    const float* bih1    = (const float*)d_in[5];
    const float* bhh1    = (const float*)d_in[6];
    const float* Wih2    = (const float*)d_in[7];
    const float* Whh2    = (const float*)d_in[8];
    const float* bih2    = (const float*)d_in[9];
    const float* bhh2    = (const float*)d_in[10];
    const float* Wv      = (const float*)d_in[11];
    const float* bv      = (const float*)d_in[12];
    const float* Wq      = (const float*)d_in[13];
    const float* bq      = (const float*)d_in[14];
    const float* wa      = (const float*)d_in[15];
    const float* ba      = (const float*)d_in[16];
    const float* W1      = (const float*)d_in[17];
    const float* b1      = (const float*)d_in[18];
    const float* W2      = (const float*)d_in[19];
    const float* b2      = (const float*)d_in[20];

    float* out     = (float*)d_out;
    float* predict = out;
    float* alphas  = out + (size_t)B_ * MAXLEN * NTOK;

    float *p_giv, *p_gip, *p_Wfq, *p_Wf2h, *p_vproj;
    SYMADDR(p_giv, g_giv);    SYMADDR(p_gip, g_gip);
    SYMADDR(p_Wfq, g_Wfq);    SYMADDR(p_Wf2h, g_Wf2h);
    SYMADDR(p_vproj, g_vproj);

    bf16 *vs_h, *vs_l, *vm_h, *vm_l, *x1p_h, *x1p_l;
    bf16 *w1h_h, *w1h_l, *w1v_h, *w1v_l, *w1p_h, *w1p_l;
    bf16 *wh1_h, *wh1_l, *wh2_h, *wh2_l;
    bf16 *wv_h, *wv_l, *w2v_h, *w2v_l, *w2x_h, *w2x_l, *ww2_h, *ww2_l;
    bf16 *wq_h, *wq_l, *w1t_h, *w1t_l, *wfq_h, *wfq_l, *wf2_h, *wf2_l;
    SYMADDR(vs_h, g_vs_h);   SYMADDR(vs_l, g_vs_l);
    SYMADDR(vm_h, g_vm_h);   SYMADDR(vm_l, g_vm_l);
    SYMADDR(x1p_h, g_x1p_h); SYMADDR(x1p_l, g_x1p_l);
    SYMADDR(w1h_h, g_wih1h_h); SYMADDR(w1h_l, g_wih1h_l);
    SYMADDR(w1v_h, g_w1v_h);   SYMADDR(w1v_l, g_w1v_l);
    SYMADDR(w1p_h, g_w1p_h);   SYMADDR(w1p_l, g_w1p_l);
    SYMADDR(wh1_h, g_whh1_h);  SYMADDR(wh1_l, g_whh1_l);
    SYMADDR(wh2_h, g_whh2_h);  SYMADDR(wh2_l, g_whh2_l);
    SYMADDR(wv_h, g_wv_h);     SYMADDR(wv_l, g_wv_l);
    SYMADDR(w2v_h, g_wih2v_h); SYMADDR(w2v_l, g_wih2v_l);
    SYMADDR(w2x_h, g_wih2x_h); SYMADDR(w2x_l, g_wih2x_l);
    SYMADDR(ww2_h, g_w2_h);    SYMADDR(ww2_l, g_w2_l);
    SYMADDR(wq_h, g_wq_h);     SYMADDR(wq_l, g_wq_l);
    SYMADDR(w1t_h, g_w1t_h);   SYMADDR(w1t_l, g_w1t_l);
    SYMADDR(wfq_h, g_wfq_h);   SYMADDR(wfq_l, g_wfq_l);
    SYMADDR(wf2_h, g_wf2h_h);  SYMADDR(wf2_l, g_wf2h_l);

    const int LOOPSMEM = 49152 + 1024;
    cudaFuncSetAttribute(tgemm_k<64>,  cudaFuncAttributeMaxDynamicSharedMemorySize,
                         TGC<64>::SMEM);
    cudaFuncSetAttribute(tgemm_k<128>, cudaFuncAttributeMaxDynamicSharedMemorySize,
                         TGC<128>::SMEM);
    cudaFuncSetAttribute(loop_kernel,  cudaFuncAttributeMaxDynamicSharedMemorySize,
                         LOOPSMEM);

    auto cv = [](const float* s, int ld, int c0, int r, int c, bf16* h, bf16* l) {
        size_t n = (size_t)r * c;
        convw_kernel<<<(unsigned)((n + 255) / 256), 256>>>(s, ld, c0, r, c, h, l);
    };

    // ---- setup ----
    meta_kernel<<<1, B_>>>(cap_len);
    zero_init_kernel<<<(B_ * HID_ + 255) / 256, 256>>>();
    permute_v_kernel<<<(unsigned)(((size_t)B_*KOBJ*VD + 255)/256), 256>>>(v);
    vmean_kernel<<<(B_ * VD + 255) / 256, 256>>>();
    build_x1p_kernel<<<(unsigned)(((size_t)TT*B_*EMB + 255)/256), 256>>>(caption);
    cv(Wih1, HID_ + VD + EMB, 1024, H3, VD,   w1v_h, w1v_l);
    cv(Wih1, HID_ + VD + EMB, 3072, H3, EMB,  w1p_h, w1p_l);
    cv(Wih1, HID_ + VD + EMB, 0,    H3, HID_, w1h_h, w1h_l);
    {   // giv = v_mean @ Wih1[:,1024:3072].T + bih1   [128 x 3072 x K=2048]
        TP P{}; P.mask = nullptr;
        P.z[0] = mkt(vm_h, vm_l, VD, w1v_h, w1v_l, VD,
                     p_giv, H3, B_, H3, VD, bih1, 0);
        tgemm_k<64><<<dim3(H3/64, 1, 1), TGC<64>::THR, TGC<64>::SMEM>>>(P);
    }
    {   // gip = x1p @ Wih1[:,3072:4096].T   [2432 x 3072 x K=1024]
        TP P{}; P.mask = nullptr;
        P.z[0] = mkt(x1p_h, x1p_l, EMB, w1p_h, w1p_l, EMB,
                     p_gip, H3, TT * B_, H3, EMB, nullptr, 0);
        tgemm_k<128><<<dim3(H3/128, (TT*B_)/128, 1), TGC<128>::THR, TGC<128>::SMEM>>>(P);
    }
    cv(Whh1, HID_, 0,    H3,   HID_, wh1_h, wh1_l);
    cv(Whh2, HID_, 0,    H3,   HID_, wh2_h, wh2_l);
    cv(Wv,   VD,   0,    HID_, VD,   wv_h,  wv_l);
    cv(Wih2, H3,   0,    H3,   VD,   w2v_h, w2v_l);
    cv(Wih2, H3,   2048, H3,   HID_, w2x_h, w2x_l);
    cv(Wq,   HID_, 0,    HID_, HID_, wq_h,  wq_l);
    cv(W2,   HID_, 0,    NTOK, HID_, ww2_h, ww2_l);
    tsplit_kernel<<<dim3(32, 32), dim3(32, 8)>>>(W1, w1t_h, w1t_l);
    {   // tensor precompute: Wfq = Wq@W1 (via W1T); Wf2h = Wih2x@W1
        TP P{}; P.mask = nullptr;
        P.z[0] = mkt(wq_h,  wq_l,  HID_, w1t_h, w1t_l, HID_,
                     p_Wfq,  HID_, HID_, HID_, HID_, nullptr, 0);
        P.z[1] = mkt(w2x_h, w2x_l, HID_, w1t_h, w1t_l, HID_,
                     p_Wf2h, HID_, H3,   HID_, HID_, nullptr, 0);
        tgemm_k<64><<<dim3(HID_/64, H3/128, 2), TGC<64>::THR, TGC<64>::SMEM>>>(P);
    }
    cv(p_Wfq,  HID_, 0, HID_, HID_, wfq_h, wfq_l);
    cv(p_Wf2h, HID_, 0, H3,   HID_, wf2_h, wf2_l);
    fusebias_kernel<<<(HID_ + H3 + 255) / 256, 256>>>(Wq, bq, b1, Wih2, bih2);
    {   // vproj = relu(v_s @ Wv.T + bv)   [4608 x 1024 x K=2048]
        TP P{}; P.mask = nullptr;
        P.z[0] = mkt(vs_h, vs_l, VD, wv_h, wv_l, VD,
                     p_vproj, HID_, B_ * KOBJ, HID_, VD, bv, 1);
        tgemm_k<128><<<dim3(HID_/128, (B_*KOBJ)/128, 1), TGC<128>::THR, TGC<128>::SMEM>>>(P);
    }

    // ---- persistent decode loop (now also computes all predict rows) ----
    loop_kernel<<<NCTA, 256, LOOPSMEM>>>(bhh1, bhh2, wa, ba, b2, alphas, predict);

    zero_tails_kernel<<<(B_ * NTOK + B_ * KOBJ + 255) / 256, 256>>>(predict, alphas);
}

// round 14
// speedup vs baseline: 1.1981x; 1.1981x over previous
#include <cuda_runtime.h>
#include <cuda_bf16.h>
#include <math.h>

// ---------------------------------------------------------------------------
// BUTDDecoder: B=128, K=36, V_DIM=2048, EMBED=1024, HID=1024, NTOKEN=10000,
// MAX_LEN=20 (T=19 decode steps).
//
// Round 14: W2 pipelined into the loop at HALF-K granularity so tasks match
// phase length: half-A (K 0..511, raw partial -> predict) rides phase 3,
// half-B (K 512..1023, += then bias+mask) rides phase 4. Phase 5 reverted
// to R12. Final timestep W2 runs full-K post-loop.
// ---------------------------------------------------------------------------

#define B_     128
#define KOBJ   36
#define VD     2048
#define EMB    1024
#define HID_   1024
#define NTOK   10000
#define MAXLEN 20
#define TT     19
#define H3     3072
#define NCTA   296
#define W2TILES 157          // ceil(10000/64)

typedef unsigned long long ull;
typedef __nv_bfloat16 bf16;

// ------------------------- scratch (device globals) ------------------------
__device__ float g_vs[B_ * KOBJ * VD];
__device__ float g_vmean[B_ * VD];
__device__ float g_vproj[B_ * KOBJ * HID_];
__device__ float g_giv[B_ * H3];
__device__ float g_gip[TT * B_ * H3];
__device__ float g_h1[B_ * HID_];
__device__ float g_h2all[(TT + 1) * B_ * HID_];
__device__ float g_gih[2][B_ * H3];
__device__ float g_gh1[2][B_ * H3];
__device__ float g_gh2[2][B_ * H3];
__device__ float g_qp[2][B_ * HID_];
__device__ float g_gi2h[2][B_ * H3];
__device__ float g_p0[4][B_ * H3];
__device__ float g_Wfq[HID_ * HID_];
__device__ float g_Wf2h[H3 * HID_];
__device__ float g_bfq[HID_];
__device__ float g_bi2f[H3];
__device__ int   g_order[B_];
__device__ int   g_dl[B_];
__device__ float g_mask[TT * B_];
__device__ int          g_barc;
__device__ volatile int g_barg;

// bf16 hi/lo operand arrays (activations)
__device__ bf16 g_vs_h[B_ * KOBJ * VD],        g_vs_l[B_ * KOBJ * VD];
__device__ bf16 g_vm_h[B_ * VD],               g_vm_l[B_ * VD];
__device__ bf16 g_x1p_h[TT * B_ * EMB],        g_x1p_l[TT * B_ * EMB];
__device__ bf16 g_h1_h[B_ * HID_],             g_h1_l[B_ * HID_];
__device__ bf16 g_h2_h[(TT + 1) * B_ * HID_],  g_h2_l[(TT + 1) * B_ * HID_];
__device__ bf16 g_attv_h[B_ * VD],             g_attv_l[B_ * VD];

// bf16 hi/lo weight arrays
__device__ bf16 g_wih1h_h[H3 * HID_],  g_wih1h_l[H3 * HID_];   // Wih1[:, :1024]
__device__ bf16 g_w1v_h[H3 * VD],      g_w1v_l[H3 * VD];       // Wih1[:, 1024:3072]
__device__ bf16 g_w1p_h[H3 * EMB],     g_w1p_l[H3 * EMB];      // Wih1[:, 3072:4096]
__device__ bf16 g_whh1_h[H3 * HID_],   g_whh1_l[H3 * HID_];
__device__ bf16 g_whh2_h[H3 * HID_],   g_whh2_l[H3 * HID_];
__device__ bf16 g_wv_h[HID_ * VD],     g_wv_l[HID_ * VD];
__device__ bf16 g_wih2v_h[H3 * VD],    g_wih2v_l[H3 * VD];     // Wih2[:, :2048]
__device__ bf16 g_wih2x_h[H3 * HID_],  g_wih2x_l[H3 * HID_];   // Wih2[:, 2048:]
__device__ bf16 g_w2_h[NTOK * HID_],   g_w2_l[NTOK * HID_];
__device__ bf16 g_wq_h[HID_ * HID_],   g_wq_l[HID_ * HID_];
__device__ bf16 g_w1t_h[HID_ * HID_],  g_w1t_l[HID_ * HID_];
__device__ bf16 g_wfq_h[HID_ * HID_],  g_wfq_l[HID_ * HID_];
__device__ bf16 g_wf2h_h[H3 * HID_],   g_wf2h_l[H3 * HID_];

// --------------------------- small helpers ---------------------------------
__device__ __forceinline__ void split2(float x, bf16& h, bf16& l) {
    h = __float2bfloat16(x);
    l = __float2bfloat16(x - __bfloat162float(h));
}
__device__ __forceinline__ unsigned smem_u32(const void* p) {
    return (unsigned)__cvta_generic_to_shared(p);
}
__device__ __forceinline__ void cpa16(unsigned dst, const void* src, int sz) {
    asm volatile("cp.async.ca.shared.global [%0], [%1], 16, %2;"
                 :: "r"(dst), "l"(src), "r"(sz));
}

#define LDM_X4(r0, r1, r2, r3, addr) \
    asm volatile("ldmatrix.sync.aligned.m8n8.x4.shared.b16 {%0,%1,%2,%3}, [%4];" \
        : "=r"(r0), "=r"(r1), "=r"(r2), "=r"(r3) : "r"(addr))

#define MMA16816(c, a, b) \
    asm volatile("mma.sync.aligned.m16n8k16.row.col.f32.bf16.bf16.f32 " \
        "{%0,%1,%2,%3}, {%4,%5,%6,%7}, {%8,%9}, {%0,%1,%2,%3};" \
        : "+f"((c)[0]), "+f"((c)[1]), "+f"((c)[2]), "+f"((c)[3]) \
        : "r"((a)[0]), "r"((a)[1]), "r"((a)[2]), "r"((a)[3]), \
          "r"((b)[0]), "r"((b)[1]))

// ----------------- host-launched tensor GEMM (big GEMMs) -------------------
struct TZ {
    const bf16 *Ahi, *Alo, *Whi, *Wlo;
    float* C; const float* bias;
    int lda, ldw, ldc, M, N, K, mode;
};
struct TP { TZ z[2]; const float* mask; };

template<int BN> struct TGC {
    static constexpr int BUF   = 32768 + BN * 256;
    static constexpr int SMEM  = 2 * BUF + 1024;
    static constexpr int THR   = BN * 2;
    static constexpr int WN    = BN / 32;
    static constexpr int RPI   = BN / 4;
    static constexpr int AIT   = 128 / RPI;
};

template<int BN>
__global__ void __launch_bounds__(TGC<BN>::THR) tgemm_k(TP p)
{
    const TZ gz = p.z[blockIdx.z];
    const int bn0 = blockIdx.x * BN;  if (bn0 >= gz.N) return;
    const int bm0 = blockIdx.y * 128; if (bm0 >= gz.M) return;
    const int tid = threadIdx.x, wid = tid >> 5, lane = tid & 31;
    const int wm = wid / TGC<BN>::WN, wn = wid % TGC<BN>::WN;

    extern __shared__ char dsm[];
    unsigned dbase = smem_u32(dsm);
    unsigned s0 = (dbase + 1023u) & ~1023u;
    unsigned sAh[2], sAl[2], sBh[2], sBl[2];
#pragma unroll
    for (int b = 0; b < 2; b++) {
        sAh[b] = s0 + b * TGC<BN>::BUF;
        sAl[b] = sAh[b] + 16384;
        sBh[b] = sAl[b] + 16384;
        sBl[b] = sBh[b] + BN * 128;
    }

    const int lrow = tid >> 3;
    const int lch  = tid & 7;
    auto load_chunk = [&](int c, int buf) {
        const int c0 = c * 64;
#pragma unroll
        for (int i = 0; i < TGC<BN>::AIT; i++) {
            int row = i * TGC<BN>::RPI + lrow;
            unsigned off = (unsigned)(row * 128) + (unsigned)(((lch ^ (row & 7)) * 16));
            cpa16(sAh[buf] + off, gz.Ahi + (size_t)(bm0 + row) * gz.lda + c0 + lch * 8, 16);
            cpa16(sAl[buf] + off, gz.Alo + (size_t)(bm0 + row) * gz.lda + c0 + lch * 8, 16);
        }
#pragma unroll
        for (int i = 0; i < 4; i++) {
            int row = i * TGC<BN>::RPI + lrow;
            unsigned off = (unsigned)(row * 128) + (unsigned)(((lch ^ (row & 7)) * 16));
            int n = bn0 + row;
            int sz = (n < gz.N) ? 16 : 0;
            int nn = (n < gz.N) ? n : 0;
            cpa16(sBh[buf] + off, gz.Whi + (size_t)nn * gz.ldw + c0 + lch * 8, sz);
            cpa16(sBl[buf] + off, gz.Wlo + (size_t)nn * gz.ldw + c0 + lch * 8, sz);
        }
        asm volatile("cp.async.commit_group;");
    };

    float acc[4][4][4];
#pragma unroll
    for (int mi = 0; mi < 4; mi++)
#pragma unroll
        for (int nj = 0; nj < 4; nj++)
#pragma unroll
            for (int e = 0; e < 4; e++) acc[mi][nj][e] = 0.f;

    const int xorkey = lane & 7;
    const int nch = gz.K / 64;
    load_chunk(0, 0);

    for (int c = 0; c < nch; c++) {
        if (c + 1 < nch) {
            load_chunk(c + 1, (c + 1) & 1);
            asm volatile("cp.async.wait_group 1;");
        } else {
            asm volatile("cp.async.wait_group 0;");
        }
        __syncthreads();
        const unsigned tAh = sAh[c & 1], tAl = sAl[c & 1];
        const unsigned tBh = sBh[c & 1], tBl = sBl[c & 1];
#pragma unroll
        for (int ks = 0; ks < 4; ks++) {
            unsigned Ah[4][4], Al[4][4];
            {
                const int arow = wm * 64 + (lane & 15);
                const unsigned aoff =
                    (unsigned)((((2 * ks) + (lane >> 4)) ^ xorkey) * 16);
#pragma unroll
                for (int mi = 0; mi < 4; mi++) {
                    unsigned ad = (unsigned)((arow + mi * 16) * 128) + aoff;
                    LDM_X4(Ah[mi][0], Ah[mi][1], Ah[mi][2], Ah[mi][3], tAh + ad);
                    LDM_X4(Al[mi][0], Al[mi][1], Al[mi][2], Al[mi][3], tAl + ad);
                }
            }
            unsigned Bh[4][2], Bl[4][2];
            {
                const int brow = wn * 32 + (lane & 7) + ((lane >> 4) << 3);
                const unsigned boff =
                    (unsigned)((((2 * ks) + ((lane >> 3) & 1)) ^ xorkey) * 16);
                unsigned r0, r1, r2, r3;
                unsigned b0 = (unsigned)(brow * 128) + boff;
                LDM_X4(r0, r1, r2, r3, tBh + b0);
                Bh[0][0] = r0; Bh[0][1] = r1; Bh[1][0] = r2; Bh[1][1] = r3;
                LDM_X4(r0, r1, r2, r3, tBh + b0 + 16 * 128);
                Bh[2][0] = r0; Bh[2][1] = r1; Bh[3][0] = r2; Bh[3][1] = r3;
                LDM_X4(r0, r1, r2, r3, tBl + b0);
                Bl[0][0] = r0; Bl[0][1] = r1; Bl[1][0] = r2; Bl[1][1] = r3;
                LDM_X4(r0, r1, r2, r3, tBl + b0 + 16 * 128);
                Bl[2][0] = r0; Bl[2][1] = r1; Bl[3][0] = r2; Bl[3][1] = r3;
            }
#pragma unroll
            for (int mi = 0; mi < 4; mi++)
#pragma unroll
                for (int nj = 0; nj < 4; nj++) {
                    MMA16816(acc[mi][nj], Ah[mi], Bh[nj]);
                    MMA16816(acc[mi][nj], Ah[mi], Bl[nj]);
                    MMA16816(acc[mi][nj], Al[mi], Bh[nj]);
                }
        }
        __syncthreads();
    }

    const int g = lane >> 2, tig = lane & 3;
    auto stc = [&](int m, int n, float val) {
        if (n >= gz.N) return;
        if (gz.bias) val += gz.bias[n];
        if (gz.mode == 1) val = fmaxf(val, 0.f);
        gz.C[(size_t)m * gz.ldc + n] = val;
    };
#pragma unroll
    for (int mi = 0; mi < 4; mi++)
#pragma unroll
        for (int nj = 0; nj < 4; nj++) {
            int row = bm0 + wm * 64 + mi * 16 + g;
            int col = bn0 + wn * 32 + nj * 8 + 2 * tig;
            stc(row,     col,     acc[mi][nj][0]);
            stc(row,     col + 1, acc[mi][nj][1]);
            stc(row + 8, col,     acc[mi][nj][2]);
            stc(row + 8, col + 1, acc[mi][nj][3]);
        }
}

// ------------------ persistent-loop device machinery ------------------------
__device__ __forceinline__ void grid_bar()
{
    __syncthreads();
    if (threadIdx.x == 0) {
        int gen = g_barg;
        __threadfence();
        if (atomicAdd(&g_barc, 1) == NCTA - 1) {
            g_barc = 0;
            __threadfence();
            g_barg = gen + 1;
        } else {
            while (g_barg == gen) __nanosleep(32);
            __threadfence();
        }
    }
    __syncthreads();
}

// one 128x64xK GEMM tile, 256 threads (8 warps: 4m x 2n), single-buffered.
__device__ __noinline__ void gemm_task(
    const bf16* __restrict__ Ah0, const bf16* __restrict__ Al0, int lda,
    const bf16* __restrict__ Wh0, const bf16* __restrict__ Wl0, int ldw,
    float* __restrict__ C, int ldc, int bn0, int Ksz,
    const float* __restrict__ bias, char* dsm)
{
    const int tid = threadIdx.x, wid = tid >> 5, lane = tid & 31;
    const int wm = wid >> 1, wn = wid & 1;

    unsigned dbase = smem_u32(dsm);
    unsigned s0 = (dbase + 1023u) & ~1023u;
    const unsigned sAh = s0;
    const unsigned sAl = sAh + 16384;
    const unsigned sBh = sAl + 16384;
    const unsigned sBl = sBh + 8192;

    const int lrow = tid >> 3;
    const int lch  = tid & 7;
    const bf16* Wb_h = Wh0 + (size_t)bn0 * ldw;
    const bf16* Wb_l = Wl0 + (size_t)bn0 * ldw;

    float acc[2][4][4];
#pragma unroll
    for (int mi = 0; mi < 2; mi++)
#pragma unroll
        for (int nj = 0; nj < 4; nj++)
#pragma unroll
            for (int e = 0; e < 4; e++) acc[mi][nj][e] = 0.f;

    const int xorkey = lane & 7;
    const int nch = Ksz / 64;

    for (int c = 0; c < nch; c++) {
        const int c0 = c * 64;
#pragma unroll
        for (int i = 0; i < 4; i++) {
            int row = i * 32 + lrow;
            unsigned off = (unsigned)(row * 128) + (unsigned)(((lch ^ (row & 7)) * 16));
            cpa16(sAh + off, Ah0 + (size_t)row * lda + c0 + lch * 8, 16);
            cpa16(sAl + off, Al0 + (size_t)row * lda + c0 + lch * 8, 16);
        }
#pragma unroll
        for (int i = 0; i < 2; i++) {
            int row = i * 32 + lrow;
            unsigned off = (unsigned)(row * 128) + (unsigned)(((lch ^ (row & 7)) * 16));
            cpa16(sBh + off, Wb_h + (size_t)row * ldw + c0 + lch * 8, 16);
            cpa16(sBl + off, Wb_l + (size_t)row * ldw + c0 + lch * 8, 16);
        }
        asm volatile("cp.async.commit_group;");
        asm volatile("cp.async.wait_group 0;");
        __syncthreads();

#pragma unroll
        for (int ks = 0; ks < 4; ks++) {
            unsigned Ahf[2][4], Alf[2][4];
            {
                const int arow = wm * 32 + (lane & 15);
                const unsigned aoff =
                    (unsigned)((((2 * ks) + (lane >> 4)) ^ xorkey) * 16);
#pragma unroll
                for (int mi = 0; mi < 2; mi++) {
                    unsigned ad = (unsigned)((arow + mi * 16) * 128) + aoff;
                    LDM_X4(Ahf[mi][0], Ahf[mi][1], Ahf[mi][2], Ahf[mi][3], sAh + ad);
                    LDM_X4(Alf[mi][0], Alf[mi][1], Alf[mi][2], Alf[mi][3], sAl + ad);
                }
            }
            unsigned Bh[4][2], Bl[4][2];
            {
                const int brow = wn * 32 + (lane & 7) + ((lane >> 4) << 3);
                const unsigned boff =
                    (unsigned)((((2 * ks) + ((lane >> 3) & 1)) ^ xorkey) * 16);
                unsigned r0, r1, r2, r3;
                unsigned b0 = (unsigned)(brow * 128) + boff;
                LDM_X4(r0, r1, r2, r3, sBh + b0);
                Bh[0][0] = r0; Bh[0][1] = r1; Bh[1][0] = r2; Bh[1][1] = r3;
                LDM_X4(r0, r1, r2, r3, sBh + b0 + 16 * 128);
                Bh[2][0] = r0; Bh[2][1] = r1; Bh[3][0] = r2; Bh[3][1] = r3;
                LDM_X4(r0, r1, r2, r3, sBl + b0);
                Bl[0][0] = r0; Bl[0][1] = r1; Bl[1][0] = r2; Bl[1][1] = r3;
                LDM_X4(r0, r1, r2, r3, sBl + b0 + 16 * 128);
                Bl[2][0] = r0; Bl[2][1] = r1; Bl[3][0] = r2; Bl[3][1] = r3;
            }
#pragma unroll
            for (int mi = 0; mi < 2; mi++)
#pragma unroll
                for (int nj = 0; nj < 4; nj++) {
                    MMA16816(acc[mi][nj], Ahf[mi], Bh[nj]);
                    MMA16816(acc[mi][nj], Ahf[mi], Bl[nj]);
                    MMA16816(acc[mi][nj], Alf[mi], Bh[nj]);
                }
        }
        __syncthreads();
    }

    const int g = lane >> 2, tig = lane & 3;
#pragma unroll
    for (int mi = 0; mi < 2; mi++)
#pragma unroll
        for (int nj = 0; nj < 4; nj++) {
            int row = wm * 32 + mi * 16 + g;
            int col = bn0 + wn * 32 + nj * 8 + 2 * tig;
            float v0 = acc[mi][nj][0], v1 = acc[mi][nj][1];
            float v2 = acc[mi][nj][2], v3 = acc[mi][nj][3];
            if (bias) {
                v0 += bias[col]; v1 += bias[col + 1];
                v2 += bias[col]; v3 += bias[col + 1];
            }
            C[(size_t)row * ldc + col]           = v0;
            C[(size_t)row * ldc + col + 1]       = v1;
            C[(size_t)(row + 8) * ldc + col]     = v2;
            C[(size_t)(row + 8) * ldc + col + 1] = v3;
        }
}

// W2 tile for timestep ts, cols [bn0, bn0+64), K slice [kbase, kbase+64*nch).
// mode 0: store raw partial into predict.
// mode 1: predict = (predict + acc + b2) * mask   (second half)
// mode 2: predict = (acc + b2) * mask             (full-K single pass)
__device__ __noinline__ void gemm_task_w2(
    int ts, int bn0, int kbase, int nch, int mode,
    const float* __restrict__ b2, float* __restrict__ predict, char* dsm)
{
    const bf16* Ah0 = g_h2_h + (size_t)(ts + 1) * B_ * HID_ + kbase;
    const bf16* Al0 = g_h2_l + (size_t)(ts + 1) * B_ * HID_ + kbase;
    const int tid = threadIdx.x, wid = tid >> 5, lane = tid & 31;
    const int wm = wid >> 1, wn = wid & 1;

    unsigned dbase = smem_u32(dsm);
    unsigned s0 = (dbase + 1023u) & ~1023u;
    const unsigned sAh = s0;
    const unsigned sAl = sAh + 16384;
    const unsigned sBh = sAl + 16384;
    const unsigned sBl = sBh + 8192;

    const int lrow = tid >> 3;
    const int lch  = tid & 7;

    float acc[2][4][4];
#pragma unroll
    for (int mi = 0; mi < 2; mi++)
#pragma unroll
        for (int nj = 0; nj < 4; nj++)
#pragma unroll
            for (int e = 0; e < 4; e++) acc[mi][nj][e] = 0.f;

    const int xorkey = lane & 7;

    for (int c = 0; c < nch; c++) {
        const int c0 = c * 64;
#pragma unroll
        for (int i = 0; i < 4; i++) {
            int row = i * 32 + lrow;
            unsigned off = (unsigned)(row * 128) + (unsigned)(((lch ^ (row & 7)) * 16));
            cpa16(sAh + off, Ah0 + (size_t)row * HID_ + c0 + lch * 8, 16);
            cpa16(sAl + off, Al0 + (size_t)row * HID_ + c0 + lch * 8, 16);
        }
#pragma unroll
        for (int i = 0; i < 2; i++) {
            int row = i * 32 + lrow;
            unsigned off = (unsigned)(row * 128) + (unsigned)(((lch ^ (row & 7)) * 16));
            int n = bn0 + row;
            int sz = (n < NTOK) ? 16 : 0;
            int nn = (n < NTOK) ? n : 0;
            cpa16(sBh + off, g_w2_h + (size_t)nn * HID_ + kbase + c0 + lch * 8, sz);
            cpa16(sBl + off, g_w2_l + (size_t)nn * HID_ + kbase + c0 + lch * 8, sz);
        }
        asm volatile("cp.async.commit_group;");
        asm volatile("cp.async.wait_group 0;");
        __syncthreads();

#pragma unroll
        for (int ks = 0; ks < 4; ks++) {
            unsigned Ahf[2][4], Alf[2][4];
            {
                const int arow = wm * 32 + (lane & 15);
                const unsigned aoff =
                    (unsigned)((((2 * ks) + (lane >> 4)) ^ xorkey) * 16);
#pragma unroll
                for (int mi = 0; mi < 2; mi++) {
                    unsigned ad = (unsigned)((arow + mi * 16) * 128) + aoff;
                    LDM_X4(Ahf[mi][0], Ahf[mi][1], Ahf[mi][2], Ahf[mi][3], sAh + ad);
                    LDM_X4(Alf[mi][0], Alf[mi][1], Alf[mi][2], Alf[mi][3], sAl + ad);
                }
            }
            unsigned Bh[4][2], Bl[4][2];
            {
                const int brow = wn * 32 + (lane & 7) + ((lane >> 4) << 3);
                const unsigned boff =
                    (unsigned)((((2 * ks) + ((lane >> 3) & 1)) ^ xorkey) * 16);
                unsigned r0, r1, r2, r3;
                unsigned b0 = (unsigned)(brow * 128) + boff;
                LDM_X4(r0, r1, r2, r3, sBh + b0);
                Bh[0][0] = r0; Bh[0][1] = r1; Bh[1][0] = r2; Bh[1][1] = r3;
                LDM_X4(r0, r1, r2, r3, sBh + b0 + 16 * 128);
                Bh[2][0] = r0; Bh[2][1] = r1; Bh[3][0] = r2; Bh[3][1] = r3;
                LDM_X4(r0, r1, r2, r3, sBl + b0);
                Bl[0][0] = r0; Bl[0][1] = r1; Bl[1][0] = r2; Bl[1][1] = r3;
                LDM_X4(r0, r1, r2, r3, sBl + b0 + 16 * 128);
                Bl[2][0] = r0; Bl[2][1] = r1; Bl[3][0] = r2; Bl[3][1] = r3;
            }
#pragma unroll
            for (int mi = 0; mi < 2; mi++)
#pragma unroll
                for (int nj = 0; nj < 4; nj++) {
                    MMA16816(acc[mi][nj], Ahf[mi], Bh[nj]);
                    MMA16816(acc[mi][nj], Ahf[mi], Bl[nj]);
                    MMA16816(acc[mi][nj], Alf[mi], Bh[nj]);
                }
        }
        __syncthreads();
    }

    const int g = lane >> 2, tig = lane & 3;
#pragma unroll
    for (int mi = 0; mi < 2; mi++)
#pragma unroll
        for (int nj = 0; nj < 4; nj++) {
            int b0r = wm * 32 + mi * 16 + g;
            int col = bn0 + wn * 32 + nj * 8 + 2 * tig;
#pragma unroll
            for (int half = 0; half < 2; half++) {
                int b = b0r + half * 8;
                size_t orow = ((size_t)b * MAXLEN + ts) * NTOK;
                float v0 = acc[mi][nj][half * 2 + 0];
                float v1 = acc[mi][nj][half * 2 + 1];
                if (mode == 0) {
                    if (col < NTOK)     predict[orow + col]     = v0;
                    if (col + 1 < NTOK) predict[orow + col + 1] = v1;
                } else {
                    float m = g_mask[ts * B_ + b];
                    if (mode == 1) {
                        if (col < NTOK)
                            predict[orow + col] =
                                (predict[orow + col] + v0 + b2[col]) * m;
                        if (col + 1 < NTOK)
                            predict[orow + col + 1] =
                                (predict[orow + col + 1] + v1 + b2[col + 1]) * m;
                    } else {
                        if (col < NTOK)
                            predict[orow + col]     = (v0 + b2[col]) * m;
                        if (col + 1 < NTOK)
                            predict[orow + col + 1] = (v1 + b2[col + 1]) * m;
                    }
                }
            }
        }
}

// ------------------------- persistent loop kernel ---------------------------
__global__ void __launch_bounds__(256, 2) loop_kernel(
    const float* __restrict__ bhh1, const float* __restrict__ bhh2,
    const float* __restrict__ wa,   const float* __restrict__ ba,
    const float* __restrict__ b2,
    float* __restrict__ alphas, float* __restrict__ predict)
{
    extern __shared__ char dsm[];
    const int cta = blockIdx.x;
    const int tid = threadIdx.x;

    for (int t = 0; t < TT; t++) {
        const bf16*  h2ph = g_h2_h + (size_t)t * B_ * HID_;
        const bf16*  h2pl = g_h2_l + (size_t)t * B_ * HID_;
        const float* h2prev = g_h2all + (size_t)t * B_ * HID_;
        float*       h2next = g_h2all + (size_t)(t + 1) * B_ * HID_;

        // ---- phase 1: stage1 (gih, gh1, gh2), 288 tasks ----
        for (int task = cta; task < 288; task += NCTA) {
            int s = task & 1, x = (task >> 1) % 48, o = task / 96;
            int ko = s * 512;
            if (o == 0)
                gemm_task(h2ph + ko, h2pl + ko, HID_,
                          g_wih1h_h + ko, g_wih1h_l + ko, HID_,
                          g_gih[s], H3, x * 64, 512, nullptr, dsm);
            else if (o == 1)
                gemm_task(g_h1_h + ko, g_h1_l + ko, HID_,
                          g_whh1_h + ko, g_whh1_l + ko, HID_,
                          g_gh1[s], H3, x * 64, 512, s == 0 ? bhh1 : nullptr, dsm);
            else
                gemm_task(h2ph + ko, h2pl + ko, HID_,
                          g_whh2_h + ko, g_whh2_l + ko, HID_,
                          g_gh2[s], H3, x * 64, 512, s == 0 ? bhh2 : nullptr, dsm);
        }
        grid_bar();

        // ---- phase 2: GRU1 pointwise ----
        {
            const float* gip = g_gip + (size_t)t * B_ * H3;
            for (int idx = cta * 256 + tid; idx < B_ * HID_; idx += NCTA * 256) {
                int b = idx >> 10, j = idx & 1023;
                size_t base = (size_t)b * H3 + j;
                float gr = g_giv[base] + gip[base] + g_gih[0][base] + g_gih[1][base];
                float gz = g_giv[base + HID_] + gip[base + HID_]
                         + g_gih[0][base + HID_] + g_gih[1][base + HID_];
                float gn = g_giv[base + 2*HID_] + gip[base + 2*HID_]
                         + g_gih[0][base + 2*HID_] + g_gih[1][base + 2*HID_];
                float ghr = g_gh1[0][base] + g_gh1[1][base];
                float ghz = g_gh1[0][base + HID_] + g_gh1[1][base + HID_];
                float ghn = g_gh1[0][base + 2*HID_] + g_gh1[1][base + 2*HID_];
                float r = 1.f / (1.f + expf(-(gr + ghr)));
                float z = 1.f / (1.f + expf(-(gz + ghz)));
                float n = tanhf(gn + r * ghn);
                float h = (1.f - z) * n + z * g_h1[idx];
                g_h1[idx] = h;
                split2(h, g_h1_h[idx], g_h1_l[idx]);
            }
        }
        grid_bar();

        // ---- phase 3: stage2 (128 tasks) + W2 half-A (157, K 0..511) ----
        if (cta < 128) {
            int task = cta;
            if (task < 32) {
                int s = task & 1, x = (task >> 1);
                int ko = s * 512;
                gemm_task(g_h1_h + ko, g_h1_l + ko, HID_,
                          g_wfq_h + ko, g_wfq_l + ko, HID_,
                          g_qp[s], HID_, x * 64, 512, nullptr, dsm);
            } else {
                int u = task - 32;
                int s = u & 1, x = (u >> 1);
                int ko = s * 512;
                gemm_task(g_h1_h + ko, g_h1_l + ko, HID_,
                          g_wf2h_h + ko, g_wf2h_l + ko, HID_,
                          g_gi2h[s], H3, x * 64, 512, nullptr, dsm);
            }
        } else if (t > 0 && cta - 128 < W2TILES) {
            gemm_task_w2(t - 1, (cta - 128) * 64, 0, 8, 0, b2, predict, dsm);
        }
        grid_bar();

        // ---- phase 4: attention (128) + W2 half-B (157, K 512..1023) ----
        if (cta < B_) {
            int b = cta;
            float* qs  = (float*)dsm;
            float* att = qs + HID_;
            for (int d = tid; d < HID_; d += 256) {
                float qv = g_qp[0][b * HID_ + d] + g_qp[1][b * HID_ + d] + g_bfq[d];
                qs[d] = fmaxf(qv, 0.f) * wa[d];
            }
            __syncthreads();
            int warp = tid >> 5, lane = tid & 31;
            for (int k = warp; k < KOBJ; k += 8) {
                const float* vp = g_vproj + ((size_t)b * KOBJ + k) * HID_;
                float s = 0.f;
                for (int d = lane; d < HID_; d += 32) s += vp[d] * qs[d];
#pragma unroll
                for (int o = 16; o; o >>= 1) s += __shfl_down_sync(0xffffffffu, s, o);
                if (lane == 0) att[k] = s + ba[0];
            }
            __syncthreads();
            if (tid == 0) {
                float mx = att[0];
                for (int k = 1; k < KOBJ; k++) mx = fmaxf(mx, att[k]);
                float ssum = 0.f;
                for (int k = 0; k < KOBJ; k++) { float e = expf(att[k] - mx); att[k] = e; ssum += e; }
                float inv = 1.f / ssum;
                for (int k = 0; k < KOBJ; k++) att[k] *= inv;
            }
            __syncthreads();
            if (tid < KOBJ) {
                float m = (t < g_dl[b]) ? 1.f : 0.f;
                alphas[((size_t)b * MAXLEN + t) * KOBJ + tid] = att[tid] * m;
            }
            for (int d = tid; d < VD; d += 256) {
                const float* vb = g_vs + (size_t)b * KOBJ * VD + d;
                float s = 0.f;
#pragma unroll 6
                for (int k = 0; k < KOBJ; k++) s += att[k] * vb[(size_t)k * VD];
                split2(s, g_attv_h[b * VD + d], g_attv_l[b * VD + d]);
            }
        } else if (t > 0 && cta - 128 < W2TILES) {
            gemm_task_w2(t - 1, (cta - 128) * 64, 512, 8, 1, b2, predict, dsm);
        }
        grid_bar();

        // ---- phase 5: gi2att (192 tasks) ----
        for (int task = cta; task < 192; task += NCTA) {
            int s = task & 3, x = task >> 2;
            int ko = s * 512;
            gemm_task(g_attv_h + ko, g_attv_l + ko, VD,
                      g_wih2v_h + ko, g_wih2v_l + ko, VD,
                      g_p0[s], H3, x * 64, 512, nullptr, dsm);
        }
        grid_bar();

        // ---- phase 6: GRU2 pointwise ----
        {
            bf16* hh = g_h2_h + (size_t)(t + 1) * B_ * HID_;
            bf16* hl = g_h2_l + (size_t)(t + 1) * B_ * HID_;
            for (int idx = cta * 256 + tid; idx < B_ * HID_; idx += NCTA * 256) {
                int b = idx >> 10, j = idx & 1023;
                size_t base = (size_t)b * H3 + j;
                float gr = g_bi2f[j], gz = g_bi2f[j + HID_], gn = g_bi2f[j + 2*HID_];
#pragma unroll
                for (int s = 0; s < 4; s++) {
                    gr += g_p0[s][base]; gz += g_p0[s][base + HID_]; gn += g_p0[s][base + 2*HID_];
                }
#pragma unroll
                for (int s = 0; s < 2; s++) {
                    gr += g_gi2h[s][base]; gz += g_gi2h[s][base + HID_]; gn += g_gi2h[s][base + 2*HID_];
                }
                float ghr = g_gh2[0][base] + g_gh2[1][base];
                float ghz = g_gh2[0][base + HID_] + g_gh2[1][base + HID_];
                float ghn = g_gh2[0][base + 2*HID_] + g_gh2[1][base + 2*HID_];
                float r = 1.f / (1.f + expf(-(gr + ghr)));
                float z = 1.f / (1.f + expf(-(gz + ghz)));
                float n = tanhf(gn + r * ghn);
                float h = (1.f - z) * n + z * h2prev[idx];
                h2next[idx] = h;
                split2(h, hh[idx], hl[idx]);
            }
        }
        grid_bar();
    }

    // ---- post-loop: final timestep's W2 (157 tasks, full K, one round) ----
    for (int task = cta; task < W2TILES; task += NCTA)
        gemm_task_w2(TT - 1, task * 64, 0, 16, 2, b2, predict, dsm);
}

// ------------------------------- small kernels -----------------------------
__global__ void meta_kernel(const int* __restrict__ cap_len)
{
    int i = threadIdx.x;
    int ci = cap_len[i];
    int rank = 0;
    for (int j = 0; j < B_; j++) {
        int cj = cap_len[j];
        if (cj > ci || (cj == ci && j < i)) rank++;
    }
    g_order[rank] = i;
    __syncthreads();
    g_dl[i] = cap_len[g_order[i]] - 1;
    __syncthreads();
    int dli = g_dl[i];
    for (int t = 0; t < TT; t++) g_mask[t * B_ + i] = (t < dli) ? 1.f : 0.f;
    if (i == 0) { g_barc = 0; g_barg = 0; }
}

__global__ void zero_init_kernel()
{
    int idx = blockIdx.x * 256 + threadIdx.x;
    if (idx < B_ * HID_) {
        g_h1[idx] = 0.f;    g_h1_h[idx] = __float2bfloat16(0.f); g_h1_l[idx] = __float2bfloat16(0.f);
        g_h2all[idx] = 0.f; g_h2_h[idx] = __float2bfloat16(0.f); g_h2_l[idx] = __float2bfloat16(0.f);
    }
}

__global__ void permute_v_kernel(const float* __restrict__ v)
{
    size_t idx = (size_t)blockIdx.x * 256 + threadIdx.x;
    if (idx >= (size_t)B_ * KOBJ * VD) return;
    int b = (int)(idx / ((size_t)KOBJ * VD));
    size_t rest = idx % ((size_t)KOBJ * VD);
    float x = v[(size_t)g_order[b] * KOBJ * VD + rest];
    g_vs[idx] = x;
    split2(x, g_vs_h[idx], g_vs_l[idx]);
}

__global__ void vmean_kernel()
{
    int idx = blockIdx.x * 256 + threadIdx.x;
    if (idx >= B_ * VD) return;
    int b = idx / VD, d = idx % VD;
    const float* p = g_vs + (size_t)b * KOBJ * VD + d;
    float s = 0.f;
#pragma unroll 6
    for (int k = 0; k < KOBJ; k++) s += p[(size_t)k * VD];
    s *= (1.f / (float)KOBJ);
    g_vmean[idx] = s;
    split2(s, g_vm_h[idx], g_vm_l[idx]);
}

__global__ void build_x1p_kernel(const float* __restrict__ caption)
{
    size_t idx = (size_t)blockIdx.x * 256 + threadIdx.x;
    if (idx >= (size_t)TT * B_ * EMB) return;
    int c = (int)(idx % EMB);
    int r = (int)(idx / EMB);
    int t = r / B_, b = r % B_;
    float val = caption[((size_t)g_order[b] * MAXLEN + t) * EMB + c];
    split2(val, g_x1p_h[idx], g_x1p_l[idx]);
}

__global__ void convw_kernel(const float* __restrict__ src, int ld, int col0,
                             int rows, int cols, bf16* __restrict__ hi,
                             bf16* __restrict__ lo)
{
    size_t idx = (size_t)blockIdx.x * 256 + threadIdx.x;
    if (idx >= (size_t)rows * cols) return;
    int r = (int)(idx / cols), c = (int)(idx % cols);
    split2(src[(size_t)r * ld + col0 + c], hi[idx], lo[idx]);
}

__global__ void tsplit_kernel(const float* __restrict__ src,
                              bf16* __restrict__ hi, bf16* __restrict__ lo)
{
    __shared__ float tile[32][33];
    int bx = blockIdx.x * 32, by = blockIdx.y * 32;
#pragma unroll
    for (int i = 0; i < 32; i += 8)
        tile[threadIdx.y + i][threadIdx.x] =
            src[(size_t)(by + threadIdx.y + i) * HID_ + bx + threadIdx.x];
    __syncthreads();
#pragma unroll
    for (int i = 0; i < 32; i += 8) {
        float vv = tile[threadIdx.x][threadIdx.y + i];
        size_t o = (size_t)(bx + threadIdx.y + i) * HID_ + by + threadIdx.x;
        split2(vv, hi[o], lo[o]);
    }
}

__global__ void fusebias_kernel(const float* __restrict__ Wq,
                                const float* __restrict__ bq,
                                const float* __restrict__ b1,
                                const float* __restrict__ Wih2,
                                const float* __restrict__ bih2)
{
    int idx = blockIdx.x * 256 + threadIdx.x;
    if (idx < HID_) {
        const float* w = Wq + (size_t)idx * HID_;
        float s = 0.f;
        for (int j = 0; j < HID_; j++) s += w[j] * b1[j];
        g_bfq[idx] = s + bq[idx];
    } else if (idx < HID_ + H3) {
        int n = idx - HID_;
        const float* w = Wih2 + (size_t)n * H3 + VD;
        float s = 0.f;
        for (int j = 0; j < HID_; j++) s += w[j] * b1[j];
        g_bi2f[n] = s + bih2[n];
    }
}

__global__ void zero_tails_kernel(float* __restrict__ predict,
                                  float* __restrict__ alphas)
{
    int idx = blockIdx.x * 256 + threadIdx.x;
    if (idx < B_ * NTOK) {
        int b = idx / NTOK, n = idx % NTOK;
        predict[((size_t)b * MAXLEN + (MAXLEN - 1)) * NTOK + n] = 0.f;
    } else if (idx < B_ * NTOK + B_ * KOBJ) {
        int r = idx - B_ * NTOK;
        int b = r / KOBJ, k = r % KOBJ;
        alphas[((size_t)b * MAXLEN + (MAXLEN - 1)) * KOBJ + k] = 0.f;
    }
}

// --------------------------------- launch ----------------------------------
static inline TZ mkt(const bf16* Ah, const bf16* Al, int lda,
                     const bf16* Wh, const bf16* Wl, int ldw,
                     float* C, int ldc, int M, int N, int K,
                     const float* bias, int mode)
{
    TZ z; z.Ahi = Ah; z.Alo = Al; z.Whi = Wh; z.Wlo = Wl;
    z.C = C; z.bias = bias; z.lda = lda; z.ldw = ldw; z.ldc = ldc;
    z.M = M; z.N = N; z.K = K; z.mode = mode;
    return z;
}

#define SYMADDR(var, sym) cudaGetSymbolAddress((void**)&var, sym)

extern "C" void kernel_launch(void* const* d_in, const int* in_sizes, int n_in,
                              void* d_out, int out_size)
{
    const float* v       = (const float*)d_in[0];
    const float* caption = (const float*)d_in[1];
    const int*   cap_len = (const int*)  d_in[2];
    const float* Wih1    = (const float*)d_in[3];
    const float* Whh1    = (const float*)d_in[4];
    const float* bih1    = (const float*)d_in[5];
    const float* bhh1    = (const float*)d_in[6];
    const float* Wih2    = (const float*)d_in[7];
    const float* Whh2    = (const float*)d_in[8];
    const float* bih2    = (const float*)d_in[9];
    const float* bhh2    = (const float*)d_in[10];
    const float* Wv      = (const float*)d_in[11];
    const float* bv      = (const float*)d_in[12];
    const float* Wq      = (const float*)d_in[13];
    const float* bq      = (const float*)d_in[14];
    const float* wa      = (const float*)d_in[15];
    const float* ba      = (const float*)d_in[16];
    const float* W1      = (const float*)d_in[17];
    const float* b1      = (const float*)d_in[18];
    const float* W2      = (const float*)d_in[19];
    const float* b2      = (const float*)d_in[20];

    float* out     = (float*)d_out;
    float* predict = out;
    float* alphas  = out + (size_t)B_ * MAXLEN * NTOK;

    float *p_giv, *p_gip, *p_Wfq, *p_Wf2h, *p_vproj;
    SYMADDR(p_giv, g_giv);    SYMADDR(p_gip, g_gip);
    SYMADDR(p_Wfq, g_Wfq);    SYMADDR(p_Wf2h, g_Wf2h);
    SYMADDR(p_vproj, g_vproj);

    bf16 *vs_h, *vs_l, *vm_h, *vm_l, *x1p_h, *x1p_l;
    bf16 *w1h_h, *w1h_l, *w1v_h, *w1v_l, *w1p_h, *w1p_l;
    bf16 *wh1_h, *wh1_l, *wh2_h, *wh2_l;
    bf16 *wv_h, *wv_l, *w2v_h, *w2v_l, *w2x_h, *w2x_l, *ww2_h, *ww2_l;
    bf16 *wq_h, *wq_l, *w1t_h, *w1t_l, *wfq_h, *wfq_l, *wf2_h, *wf2_l;
    SYMADDR(vs_h, g_vs_h);   SYMADDR(vs_l, g_vs_l);
    SYMADDR(vm_h, g_vm_h);   SYMADDR(vm_l, g_vm_l);
    SYMADDR(x1p_h, g_x1p_h); SYMADDR(x1p_l, g_x1p_l);
    SYMADDR(w1h_h, g_wih1h_h); SYMADDR(w1h_l, g_wih1h_l);
    SYMADDR(w1v_h, g_w1v_h);   SYMADDR(w1v_l, g_w1v_l);
    SYMADDR(w1p_h, g_w1p_h);   SYMADDR(w1p_l, g_w1p_l);
    SYMADDR(wh1_h, g_whh1_h);  SYMADDR(wh1_l, g_whh1_l);
    SYMADDR(wh2_h, g_whh2_h);  SYMADDR(wh2_l, g_whh2_l);
    SYMADDR(wv_h, g_wv_h);     SYMADDR(wv_l, g_wv_l);
    SYMADDR(w2v_h, g_wih2v_h); SYMADDR(w2v_l, g_wih2v_l);
    SYMADDR(w2x_h, g_wih2x_h); SYMADDR(w2x_l, g_wih2x_l);
    SYMADDR(ww2_h, g_w2_h);    SYMADDR(ww2_l, g_w2_l);
    SYMADDR(wq_h, g_wq_h);     SYMADDR(wq_l, g_wq_l);
    SYMADDR(w1t_h, g_w1t_h);   SYMADDR(w1t_l, g_w1t_l);
    SYMADDR(wfq_h, g_wfq_h);   SYMADDR(wfq_l, g_wfq_l);
    SYMADDR(wf2_h, g_wf2h_h);  SYMADDR(wf2_l, g_wf2h_l);

    const int LOOPSMEM = 49152 + 1024;
    cudaFuncSetAttribute(tgemm_k<64>,  cudaFuncAttributeMaxDynamicSharedMemorySize,
                         TGC<64>::SMEM);
    cudaFuncSetAttribute(tgemm_k<128>, cudaFuncAttributeMaxDynamicSharedMemorySize,
                         TGC<128>::SMEM);
    cudaFuncSetAttribute(loop_kernel,  cudaFuncAttributeMaxDynamicSharedMemorySize,
                         LOOPSMEM);

    auto cv = [](const float* s, int ld, int c0, int r, int c, bf16* h, bf16* l) {
        size_t n = (size_t)r * c;
        convw_kernel<<<(unsigned)((n + 255) / 256), 256>>>(s, ld, c0, r, c, h, l);
    };

    // ---- setup ----
    meta_kernel<<<1, B_>>>(cap_len);
    zero_init_kernel<<<(B_ * HID_ + 255) / 256, 256>>>();
    permute_v_kernel<<<(unsigned)(((size_t)B_*KOBJ*VD + 255)/256), 256>>>(v);
    vmean_kernel<<<(B_ * VD + 255) / 256, 256>>>();
    build_x1p_kernel<<<(unsigned)(((size_t)TT*B_*EMB + 255)/256), 256>>>(caption);
    cv(Wih1, HID_ + VD + EMB, 1024, H3, VD,   w1v_h, w1v_l);
    cv(Wih1, HID_ + VD + EMB, 3072, H3, EMB,  w1p_h, w1p_l);
    cv(Wih1, HID_ + VD + EMB, 0,    H3, HID_, w1h_h, w1h_l);
    {   // giv = v_mean @ Wih1[:,1024:3072].T + bih1   [128 x 3072 x K=2048]
        TP P{}; P.mask = nullptr;
        P.z[0] = mkt(vm_h, vm_l, VD, w1v_h, w1v_l, VD,
                     p_giv, H3, B_, H3, VD, bih1, 0);
        tgemm_k<64><<<dim3(H3/64, 1, 1), TGC<64>::THR, TGC<64>::SMEM>>>(P);
    }
    {   // gip = x1p @ Wih1[:,3072:4096].T   [2432 x 3072 x K=1024]
        TP P{}; P.mask = nullptr;
        P.z[0] = mkt(x1p_h, x1p_l, EMB, w1p_h, w1p_l, EMB,
                     p_gip, H3, TT * B_, H3, EMB, nullptr, 0);
        tgemm_k<128><<<dim3(H3/128, (TT*B_)/128, 1), TGC<128>::THR, TGC<128>::SMEM>>>(P);
    }
    cv(Whh1, HID_, 0,    H3,   HID_, wh1_h, wh1_l);
    cv(Whh2, HID_, 0,    H3,   HID_, wh2_h, wh2_l);
    cv(Wv,   VD,   0,    HID_, VD,   wv_h,  wv_l);
    cv(Wih2, H3,   0,    H3,   VD,   w2v_h, w2v_l);
    cv(Wih2, H3,   2048, H3,   HID_, w2x_h, w2x_l);
    cv(Wq,   HID_, 0,    HID_, HID_, wq_h,  wq_l);
    cv(W2,   HID_, 0,    NTOK, HID_, ww2_h, ww2_l);
    tsplit_kernel<<<dim3(32, 32), dim3(32, 8)>>>(W1, w1t_h, w1t_l);
    {   // tensor precompute: Wfq = Wq@W1 (via W1T); Wf2h = Wih2x@W1
        TP P{}; P.mask = nullptr;
        P.z[0] = mkt(wq_h,  wq_l,  HID_, w1t_h, w1t_l, HID_,
                     p_Wfq,  HID_, HID_, HID_, HID_, nullptr, 0);
        P.z[1] = mkt(w2x_h, w2x_l, HID_, w1t_h, w1t_l, HID_,
                     p_Wf2h, HID_, H3,   HID_, HID_, nullptr, 0);
        tgemm_k<64><<<dim3(HID_/64, H3/128, 2), TGC<64>::THR, TGC<64>::SMEM>>>(P);
    }
    cv(p_Wfq,  HID_, 0, HID_, HID_, wfq_h, wfq_l);
    cv(p_Wf2h, HID_, 0, H3,   HID_, wf2_h, wf2_l);
    fusebias_kernel<<<(HID_ + H3 + 255) / 256, 256>>>(Wq, bq, b1, Wih2, bih2);
    {   // vproj = relu(v_s @ Wv.T + bv)   [4608 x 1024 x K=2048]
        TP P{}; P.mask = nullptr;
        P.z[0] = mkt(vs_h, vs_l, VD, wv_h, wv_l, VD,
                     p_vproj, HID_, B_ * KOBJ, HID_, VD, bv, 1);
        tgemm_k<128><<<dim3(HID_/128, (B_*KOBJ)/128, 1), TGC<128>::THR, TGC<128>::SMEM>>>(P);
    }

    // ---- persistent decode loop (computes all predict rows too) ----
    loop_kernel<<<NCTA, 256, LOOPSMEM>>>(bhh1, bhh2, wa, ba, b2, alphas, predict);

    zero_tails_kernel<<<(B_ * NTOK + B_ * KOBJ + 255) / 256, 256>>>(predict, alphas);
}

// round 15
// speedup vs baseline: 1.2198x; 1.0182x over previous
#include <cuda_runtime.h>
#include <cuda_bf16.h>
#include <math.h>

// ---------------------------------------------------------------------------
// BUTDDecoder: B=128, K=36, V_DIM=2048, EMBED=1024, HID=1024, NTOKEN=10000,
// MAX_LEN=20 (T=19 decode steps).
//
// Round 15:
//  * in-loop gemm_task / gemm_task_w2 restored to 2-stage cp.async double
//    buffering (2 CTAs/SM x 97KB = 194KB <= 228KB smem carveout).
//  * all 10 weight converts merged into one mega-convert kernel.
//  * zero_tails absorbed into the persistent loop's postlude.
// ---------------------------------------------------------------------------

#define B_     128
#define KOBJ   36
#define VD     2048
#define EMB    1024
#define HID_   1024
#define NTOK   10000
#define MAXLEN 20
#define TT     19
#define H3     3072
#define NCTA   296
#define W2TILES 157          // ceil(10000/64)

typedef unsigned long long ull;
typedef __nv_bfloat16 bf16;

// ------------------------- scratch (device globals) ------------------------
__device__ float g_vs[B_ * KOBJ * VD];
__device__ float g_vmean[B_ * VD];
__device__ float g_vproj[B_ * KOBJ * HID_];
__device__ float g_giv[B_ * H3];
__device__ float g_gip[TT * B_ * H3];
__device__ float g_h1[B_ * HID_];
__device__ float g_h2all[(TT + 1) * B_ * HID_];
__device__ float g_gih[2][B_ * H3];
__device__ float g_gh1[2][B_ * H3];
__device__ float g_gh2[2][B_ * H3];
__device__ float g_qp[2][B_ * HID_];
__device__ float g_gi2h[2][B_ * H3];
__device__ float g_p0[4][B_ * H3];
__device__ float g_Wfq[HID_ * HID_];
__device__ float g_Wf2h[H3 * HID_];
__device__ float g_bfq[HID_];
__device__ float g_bi2f[H3];
__device__ int   g_order[B_];
__device__ int   g_dl[B_];
__device__ float g_mask[TT * B_];
__device__ int          g_barc;
__device__ volatile int g_barg;

// bf16 hi/lo operand arrays (activations)
__device__ bf16 g_vs_h[B_ * KOBJ * VD],        g_vs_l[B_ * KOBJ * VD];
__device__ bf16 g_vm_h[B_ * VD],               g_vm_l[B_ * VD];
__device__ bf16 g_x1p_h[TT * B_ * EMB],        g_x1p_l[TT * B_ * EMB];
__device__ bf16 g_h1_h[B_ * HID_],             g_h1_l[B_ * HID_];
__device__ bf16 g_h2_h[(TT + 1) * B_ * HID_],  g_h2_l[(TT + 1) * B_ * HID_];
__device__ bf16 g_attv_h[B_ * VD],             g_attv_l[B_ * VD];

// bf16 hi/lo weight arrays
__device__ bf16 g_wih1h_h[H3 * HID_],  g_wih1h_l[H3 * HID_];   // Wih1[:, :1024]
__device__ bf16 g_w1v_h[H3 * VD],      g_w1v_l[H3 * VD];       // Wih1[:, 1024:3072]
__device__ bf16 g_w1p_h[H3 * EMB],     g_w1p_l[H3 * EMB];      // Wih1[:, 3072:4096]
__device__ bf16 g_whh1_h[H3 * HID_],   g_whh1_l[H3 * HID_];
__device__ bf16 g_whh2_h[H3 * HID_],   g_whh2_l[H3 * HID_];
__device__ bf16 g_wv_h[HID_ * VD],     g_wv_l[HID_ * VD];
__device__ bf16 g_wih2v_h[H3 * VD],    g_wih2v_l[H3 * VD];     // Wih2[:, :2048]
__device__ bf16 g_wih2x_h[H3 * HID_],  g_wih2x_l[H3 * HID_];   // Wih2[:, 2048:]
__device__ bf16 g_w2_h[NTOK * HID_],   g_w2_l[NTOK * HID_];
__device__ bf16 g_wq_h[HID_ * HID_],   g_wq_l[HID_ * HID_];
__device__ bf16 g_w1t_h[HID_ * HID_],  g_w1t_l[HID_ * HID_];
__device__ bf16 g_wfq_h[HID_ * HID_],  g_wfq_l[HID_ * HID_];
__device__ bf16 g_wf2h_h[H3 * HID_],   g_wf2h_l[H3 * HID_];

// --------------------------- small helpers ---------------------------------
__device__ __forceinline__ void split2(float x, bf16& h, bf16& l) {
    h = __float2bfloat16(x);
    l = __float2bfloat16(x - __bfloat162float(h));
}
__device__ __forceinline__ unsigned smem_u32(const void* p) {
    return (unsigned)__cvta_generic_to_shared(p);
}
__device__ __forceinline__ void cpa16(unsigned dst, const void* src, int sz) {
    asm volatile("cp.async.ca.shared.global [%0], [%1], 16, %2;"
                 :: "r"(dst), "l"(src), "r"(sz));
}

#define LDM_X4(r0, r1, r2, r3, addr) \
    asm volatile("ldmatrix.sync.aligned.m8n8.x4.shared.b16 {%0,%1,%2,%3}, [%4];" \
        : "=r"(r0), "=r"(r1), "=r"(r2), "=r"(r3) : "r"(addr))

#define MMA16816(c, a, b) \
    asm volatile("mma.sync.aligned.m16n8k16.row.col.f32.bf16.bf16.f32 " \
        "{%0,%1,%2,%3}, {%4,%5,%6,%7}, {%8,%9}, {%0,%1,%2,%3};" \
        : "+f"((c)[0]), "+f"((c)[1]), "+f"((c)[2]), "+f"((c)[3]) \
        : "r"((a)[0]), "r"((a)[1]), "r"((a)[2]), "r"((a)[3]), \
          "r"((b)[0]), "r"((b)[1]))

// ----------------- host-launched tensor GEMM (big GEMMs) -------------------
struct TZ {
    const bf16 *Ahi, *Alo, *Whi, *Wlo;
    float* C; const float* bias;
    int lda, ldw, ldc, M, N, K, mode;
};
struct TP { TZ z[2]; const float* mask; };

template<int BN> struct TGC {
    static constexpr int BUF   = 32768 + BN * 256;
    static constexpr int SMEM  = 2 * BUF + 1024;
    static constexpr int THR   = BN * 2;
    static constexpr int WN    = BN / 32;
    static constexpr int RPI   = BN / 4;
    static constexpr int AIT   = 128 / RPI;
};

template<int BN>
__global__ void __launch_bounds__(TGC<BN>::THR) tgemm_k(TP p)
{
    const TZ gz = p.z[blockIdx.z];
    const int bn0 = blockIdx.x * BN;  if (bn0 >= gz.N) return;
    const int bm0 = blockIdx.y * 128; if (bm0 >= gz.M) return;
    const int tid = threadIdx.x, wid = tid >> 5, lane = tid & 31;
    const int wm = wid / TGC<BN>::WN, wn = wid % TGC<BN>::WN;

    extern __shared__ char dsm[];
    unsigned dbase = smem_u32(dsm);
    unsigned s0 = (dbase + 1023u) & ~1023u;
    unsigned sAh[2], sAl[2], sBh[2], sBl[2];
#pragma unroll
    for (int b = 0; b < 2; b++) {
        sAh[b] = s0 + b * TGC<BN>::BUF;
        sAl[b] = sAh[b] + 16384;
        sBh[b] = sAl[b] + 16384;
        sBl[b] = sBh[b] + BN * 128;
    }

    const int lrow = tid >> 3;
    const int lch  = tid & 7;
    auto load_chunk = [&](int c, int buf) {
        const int c0 = c * 64;
#pragma unroll
        for (int i = 0; i < TGC<BN>::AIT; i++) {
            int row = i * TGC<BN>::RPI + lrow;
            unsigned off = (unsigned)(row * 128) + (unsigned)(((lch ^ (row & 7)) * 16));
            cpa16(sAh[buf] + off, gz.Ahi + (size_t)(bm0 + row) * gz.lda + c0 + lch * 8, 16);
            cpa16(sAl[buf] + off, gz.Alo + (size_t)(bm0 + row) * gz.lda + c0 + lch * 8, 16);
        }
#pragma unroll
        for (int i = 0; i < 4; i++) {
            int row = i * TGC<BN>::RPI + lrow;
            unsigned off = (unsigned)(row * 128) + (unsigned)(((lch ^ (row & 7)) * 16));
            int n = bn0 + row;
            int sz = (n < gz.N) ? 16 : 0;
            int nn = (n < gz.N) ? n : 0;
            cpa16(sBh[buf] + off, gz.Whi + (size_t)nn * gz.ldw + c0 + lch * 8, sz);
            cpa16(sBl[buf] + off, gz.Wlo + (size_t)nn * gz.ldw + c0 + lch * 8, sz);
        }
        asm volatile("cp.async.commit_group;");
    };

    float acc[4][4][4];
#pragma unroll
    for (int mi = 0; mi < 4; mi++)
#pragma unroll
        for (int nj = 0; nj < 4; nj++)
#pragma unroll
            for (int e = 0; e < 4; e++) acc[mi][nj][e] = 0.f;

    const int xorkey = lane & 7;
    const int nch = gz.K / 64;
    load_chunk(0, 0);

    for (int c = 0; c < nch; c++) {
        if (c + 1 < nch) {
            load_chunk(c + 1, (c + 1) & 1);
            asm volatile("cp.async.wait_group 1;");
        } else {
            asm volatile("cp.async.wait_group 0;");
        }
        __syncthreads();
        const unsigned tAh = sAh[c & 1], tAl = sAl[c & 1];
        const unsigned tBh = sBh[c & 1], tBl = sBl[c & 1];
#pragma unroll
        for (int ks = 0; ks < 4; ks++) {
            unsigned Ah[4][4], Al[4][4];
            {
                const int arow = wm * 64 + (lane & 15);
                const unsigned aoff =
                    (unsigned)((((2 * ks) + (lane >> 4)) ^ xorkey) * 16);
#pragma unroll
                for (int mi = 0; mi < 4; mi++) {
                    unsigned ad = (unsigned)((arow + mi * 16) * 128) + aoff;
                    LDM_X4(Ah[mi][0], Ah[mi][1], Ah[mi][2], Ah[mi][3], tAh + ad);
                    LDM_X4(Al[mi][0], Al[mi][1], Al[mi][2], Al[mi][3], tAl + ad);
                }
            }
            unsigned Bh[4][2], Bl[4][2];
            {
                const int brow = wn * 32 + (lane & 7) + ((lane >> 4) << 3);
                const unsigned boff =
                    (unsigned)((((2 * ks) + ((lane >> 3) & 1)) ^ xorkey) * 16);
                unsigned r0, r1, r2, r3;
                unsigned b0 = (unsigned)(brow * 128) + boff;
                LDM_X4(r0, r1, r2, r3, tBh + b0);
                Bh[0][0] = r0; Bh[0][1] = r1; Bh[1][0] = r2; Bh[1][1] = r3;
                LDM_X4(r0, r1, r2, r3, tBh + b0 + 16 * 128);
                Bh[2][0] = r0; Bh[2][1] = r1; Bh[3][0] = r2; Bh[3][1] = r3;
                LDM_X4(r0, r1, r2, r3, tBl + b0);
                Bl[0][0] = r0; Bl[0][1] = r1; Bl[1][0] = r2; Bl[1][1] = r3;
                LDM_X4(r0, r1, r2, r3, tBl + b0 + 16 * 128);
                Bl[2][0] = r0; Bl[2][1] = r1; Bl[3][0] = r2; Bl[3][1] = r3;
            }
#pragma unroll
            for (int mi = 0; mi < 4; mi++)
#pragma unroll
                for (int nj = 0; nj < 4; nj++) {
                    MMA16816(acc[mi][nj], Ah[mi], Bh[nj]);
                    MMA16816(acc[mi][nj], Ah[mi], Bl[nj]);
                    MMA16816(acc[mi][nj], Al[mi], Bh[nj]);
                }
        }
        __syncthreads();
    }

    const int g = lane >> 2, tig = lane & 3;
    auto stc = [&](int m, int n, float val) {
        if (n >= gz.N) return;
        if (gz.bias) val += gz.bias[n];
        if (gz.mode == 1) val = fmaxf(val, 0.f);
        gz.C[(size_t)m * gz.ldc + n] = val;
    };
#pragma unroll
    for (int mi = 0; mi < 4; mi++)
#pragma unroll
        for (int nj = 0; nj < 4; nj++) {
            int row = bm0 + wm * 64 + mi * 16 + g;
            int col = bn0 + wn * 32 + nj * 8 + 2 * tig;
            stc(row,     col,     acc[mi][nj][0]);
            stc(row,     col + 1, acc[mi][nj][1]);
            stc(row + 8, col,     acc[mi][nj][2]);
            stc(row + 8, col + 1, acc[mi][nj][3]);
        }
}

// ------------------ persistent-loop device machinery ------------------------
__device__ __forceinline__ void grid_bar()
{
    __syncthreads();
    if (threadIdx.x == 0) {
        int gen = g_barg;
        __threadfence();
        if (atomicAdd(&g_barc, 1) == NCTA - 1) {
            g_barc = 0;
            __threadfence();
            g_barg = gen + 1;
        } else {
            while (g_barg == gen) __nanosleep(32);
            __threadfence();
        }
    }
    __syncthreads();
}

#define LBUF 49152   // per-stage smem inside the loop (Ah16K|Al16K|Bh8K|Bl8K)

// one 128x64xK GEMM tile, 256 threads (8 warps: 4m x 2n), double-buffered.
__device__ __noinline__ void gemm_task(
    const bf16* __restrict__ Ah0, const bf16* __restrict__ Al0, int lda,
    const bf16* __restrict__ Wh0, const bf16* __restrict__ Wl0, int ldw,
    float* __restrict__ C, int ldc, int bn0, int Ksz,
    const float* __restrict__ bias, char* dsm)
{
    const int tid = threadIdx.x, wid = tid >> 5, lane = tid & 31;
    const int wm = wid >> 1, wn = wid & 1;

    unsigned dbase = smem_u32(dsm);
    unsigned s0 = (dbase + 1023u) & ~1023u;
    unsigned sAh[2], sAl[2], sBh[2], sBl[2];
#pragma unroll
    for (int b = 0; b < 2; b++) {
        sAh[b] = s0 + b * LBUF;
        sAl[b] = sAh[b] + 16384;
        sBh[b] = sAl[b] + 16384;
        sBl[b] = sBh[b] + 8192;
    }

    const int lrow = tid >> 3;
    const int lch  = tid & 7;
    const bf16* Wb_h = Wh0 + (size_t)bn0 * ldw;
    const bf16* Wb_l = Wl0 + (size_t)bn0 * ldw;
    auto load_chunk = [&](int c, int buf) {
        const int c0 = c * 64;
#pragma unroll
        for (int i = 0; i < 4; i++) {
            int row = i * 32 + lrow;
            unsigned off = (unsigned)(row * 128) + (unsigned)(((lch ^ (row & 7)) * 16));
            cpa16(sAh[buf] + off, Ah0 + (size_t)row * lda + c0 + lch * 8, 16);
            cpa16(sAl[buf] + off, Al0 + (size_t)row * lda + c0 + lch * 8, 16);
        }
#pragma unroll
        for (int i = 0; i < 2; i++) {
            int row = i * 32 + lrow;
            unsigned off = (unsigned)(row * 128) + (unsigned)(((lch ^ (row & 7)) * 16));
            cpa16(sBh[buf] + off, Wb_h + (size_t)row * ldw + c0 + lch * 8, 16);
            cpa16(sBl[buf] + off, Wb_l + (size_t)row * ldw + c0 + lch * 8, 16);
        }
        asm volatile("cp.async.commit_group;");
    };

    float acc[2][4][4];
#pragma unroll
    for (int mi = 0; mi < 2; mi++)
#pragma unroll
        for (int nj = 0; nj < 4; nj++)
#pragma unroll
            for (int e = 0; e < 4; e++) acc[mi][nj][e] = 0.f;

    const int xorkey = lane & 7;
    const int nch = Ksz / 64;
    load_chunk(0, 0);

    for (int c = 0; c < nch; c++) {
        if (c + 1 < nch) {
            load_chunk(c + 1, (c + 1) & 1);
            asm volatile("cp.async.wait_group 1;");
        } else {
            asm volatile("cp.async.wait_group 0;");
        }
        __syncthreads();
        const unsigned tAh = sAh[c & 1], tAl = sAl[c & 1];
        const unsigned tBh = sBh[c & 1], tBl = sBl[c & 1];

#pragma unroll
        for (int ks = 0; ks < 4; ks++) {
            unsigned Ahf[2][4], Alf[2][4];
            {
                const int arow = wm * 32 + (lane & 15);
                const unsigned aoff =
                    (unsigned)((((2 * ks) + (lane >> 4)) ^ xorkey) * 16);
#pragma unroll
                for (int mi = 0; mi < 2; mi++) {
                    unsigned ad = (unsigned)((arow + mi * 16) * 128) + aoff;
                    LDM_X4(Ahf[mi][0], Ahf[mi][1], Ahf[mi][2], Ahf[mi][3], tAh + ad);
                    LDM_X4(Alf[mi][0], Alf[mi][1], Alf[mi][2], Alf[mi][3], tAl + ad);
                }
            }
            unsigned Bh[4][2], Bl[4][2];
            {
                const int brow = wn * 32 + (lane & 7) + ((lane >> 4) << 3);
                const unsigned boff =
                    (unsigned)((((2 * ks) + ((lane >> 3) & 1)) ^ xorkey) * 16);
                unsigned r0, r1, r2, r3;
                unsigned b0 = (unsigned)(brow * 128) + boff;
                LDM_X4(r0, r1, r2, r3, tBh + b0);
                Bh[0][0] = r0; Bh[0][1] = r1; Bh[1][0] = r2; Bh[1][1] = r3;
                LDM_X4(r0, r1, r2, r3, tBh + b0 + 16 * 128);
                Bh[2][0] = r0; Bh[2][1] = r1; Bh[3][0] = r2; Bh[3][1] = r3;
                LDM_X4(r0, r1, r2, r3, tBl + b0);
                Bl[0][0] = r0; Bl[0][1] = r1; Bl[1][0] = r2; Bl[1][1] = r3;
                LDM_X4(r0, r1, r2, r3, tBl + b0 + 16 * 128);
                Bl[2][0] = r0; Bl[2][1] = r1; Bl[3][0] = r2; Bl[3][1] = r3;
            }
#pragma unroll
            for (int mi = 0; mi < 2; mi++)
#pragma unroll
                for (int nj = 0; nj < 4; nj++) {
                    MMA16816(acc[mi][nj], Ahf[mi], Bh[nj]);
                    MMA16816(acc[mi][nj], Ahf[mi], Bl[nj]);
                    MMA16816(acc[mi][nj], Alf[mi], Bh[nj]);
                }
        }
        __syncthreads();
    }

    const int g = lane >> 2, tig = lane & 3;
#pragma unroll
    for (int mi = 0; mi < 2; mi++)
#pragma unroll
        for (int nj = 0; nj < 4; nj++) {
            int row = wm * 32 + mi * 16 + g;
            int col = bn0 + wn * 32 + nj * 8 + 2 * tig;
            float v0 = acc[mi][nj][0], v1 = acc[mi][nj][1];
            float v2 = acc[mi][nj][2], v3 = acc[mi][nj][3];
            if (bias) {
                v0 += bias[col]; v1 += bias[col + 1];
                v2 += bias[col]; v3 += bias[col + 1];
            }
            C[(size_t)row * ldc + col]           = v0;
            C[(size_t)row * ldc + col + 1]       = v1;
            C[(size_t)(row + 8) * ldc + col]     = v2;
            C[(size_t)(row + 8) * ldc + col + 1] = v3;
        }
}

// W2 tile for timestep ts, cols [bn0, bn0+64), K slice [kbase, kbase+64*nch).
// mode 0: raw partial; mode 1: += then bias+mask; mode 2: full single pass.
__device__ __noinline__ void gemm_task_w2(
    int ts, int bn0, int kbase, int nch, int mode,
    const float* __restrict__ b2, float* __restrict__ predict, char* dsm)
{
    const bf16* Ah0 = g_h2_h + (size_t)(ts + 1) * B_ * HID_ + kbase;
    const bf16* Al0 = g_h2_l + (size_t)(ts + 1) * B_ * HID_ + kbase;
    const int tid = threadIdx.x, wid = tid >> 5, lane = tid & 31;
    const int wm = wid >> 1, wn = wid & 1;

    unsigned dbase = smem_u32(dsm);
    unsigned s0 = (dbase + 1023u) & ~1023u;
    unsigned sAh[2], sAl[2], sBh[2], sBl[2];
#pragma unroll
    for (int b = 0; b < 2; b++) {
        sAh[b] = s0 + b * LBUF;
        sAl[b] = sAh[b] + 16384;
        sBh[b] = sAl[b] + 16384;
        sBl[b] = sBh[b] + 8192;
    }

    const int lrow = tid >> 3;
    const int lch  = tid & 7;
    auto load_chunk = [&](int c, int buf) {
        const int c0 = c * 64;
#pragma unroll
        for (int i = 0; i < 4; i++) {
            int row = i * 32 + lrow;
            unsigned off = (unsigned)(row * 128) + (unsigned)(((lch ^ (row & 7)) * 16));
            cpa16(sAh[buf] + off, Ah0 + (size_t)row * HID_ + c0 + lch * 8, 16);
            cpa16(sAl[buf] + off, Al0 + (size_t)row * HID_ + c0 + lch * 8, 16);
        }
#pragma unroll
        for (int i = 0; i < 2; i++) {
            int row = i * 32 + lrow;
            unsigned off = (unsigned)(row * 128) + (unsigned)(((lch ^ (row & 7)) * 16));
            int n = bn0 + row;
            int sz = (n < NTOK) ? 16 : 0;
            int nn = (n < NTOK) ? n : 0;
            cpa16(sBh[buf] + off, g_w2_h + (size_t)nn * HID_ + kbase + c0 + lch * 8, sz);
            cpa16(sBl[buf] + off, g_w2_l + (size_t)nn * HID_ + kbase + c0 + lch * 8, sz);
        }
        asm volatile("cp.async.commit_group;");
    };

    float acc[2][4][4];
#pragma unroll
    for (int mi = 0; mi < 2; mi++)
#pragma unroll
        for (int nj = 0; nj < 4; nj++)
#pragma unroll
            for (int e = 0; e < 4; e++) acc[mi][nj][e] = 0.f;

    const int xorkey = lane & 7;
    load_chunk(0, 0);

    for (int c = 0; c < nch; c++) {
        if (c + 1 < nch) {
            load_chunk(c + 1, (c + 1) & 1);
            asm volatile("cp.async.wait_group 1;");
        } else {
            asm volatile("cp.async.wait_group 0;");
        }
        __syncthreads();
        const unsigned tAh = sAh[c & 1], tAl = sAl[c & 1];
        const unsigned tBh = sBh[c & 1], tBl = sBl[c & 1];

#pragma unroll
        for (int ks = 0; ks < 4; ks++) {
            unsigned Ahf[2][4], Alf[2][4];
            {
                const int arow = wm * 32 + (lane & 15);
                const unsigned aoff =
                    (unsigned)((((2 * ks) + (lane >> 4)) ^ xorkey) * 16);
#pragma unroll
                for (int mi = 0; mi < 2; mi++) {
                    unsigned ad = (unsigned)((arow + mi * 16) * 128) + aoff;
                    LDM_X4(Ahf[mi][0], Ahf[mi][1], Ahf[mi][2], Ahf[mi][3], tAh + ad);
                    LDM_X4(Alf[mi][0], Alf[mi][1], Alf[mi][2], Alf[mi][3], tAl + ad);
                }
            }
            unsigned Bh[4][2], Bl[4][2];
            {
                const int brow = wn * 32 + (lane & 7) + ((lane >> 4) << 3);
                const unsigned boff =
                    (unsigned)((((2 * ks) + ((lane >> 3) & 1)) ^ xorkey) * 16);
                unsigned r0, r1, r2, r3;
                unsigned b0 = (unsigned)(brow * 128) + boff;
                LDM_X4(r0, r1, r2, r3, tBh + b0);
                Bh[0][0] = r0; Bh[0][1] = r1; Bh[1][0] = r2; Bh[1][1] = r3;
                LDM_X4(r0, r1, r2, r3, tBh + b0 + 16 * 128);
                Bh[2][0] = r0; Bh[2][1] = r1; Bh[3][0] = r2; Bh[3][1] = r3;
                LDM_X4(r0, r1, r2, r3, tBl + b0);
                Bl[0][0] = r0; Bl[0][1] = r1; Bl[1][0] = r2; Bl[1][1] = r3;
                LDM_X4(r0, r1, r2, r3, tBl + b0 + 16 * 128);
                Bl[2][0] = r0; Bl[2][1] = r1; Bl[3][0] = r2; Bl[3][1] = r3;
            }
#pragma unroll
            for (int mi = 0; mi < 2; mi++)
#pragma unroll
                for (int nj = 0; nj < 4; nj++) {
                    MMA16816(acc[mi][nj], Ahf[mi], Bh[nj]);
                    MMA16816(acc[mi][nj], Ahf[mi], Bl[nj]);
                    MMA16816(acc[mi][nj], Alf[mi], Bh[nj]);
                }
        }
        __syncthreads();
    }

    const int g = lane >> 2, tig = lane & 3;
#pragma unroll
    for (int mi = 0; mi < 2; mi++)
#pragma unroll
        for (int nj = 0; nj < 4; nj++) {
            int b0r = wm * 32 + mi * 16 + g;
            int col = bn0 + wn * 32 + nj * 8 + 2 * tig;
#pragma unroll
            for (int half = 0; half < 2; half++) {
                int b = b0r + half * 8;
                size_t orow = ((size_t)b * MAXLEN + ts) * NTOK;
                float v0 = acc[mi][nj][half * 2 + 0];
                float v1 = acc[mi][nj][half * 2 + 1];
                if (mode == 0) {
                    if (col < NTOK)     predict[orow + col]     = v0;
                    if (col + 1 < NTOK) predict[orow + col + 1] = v1;
                } else {
                    float m = g_mask[ts * B_ + b];
                    if (mode == 1) {
                        if (col < NTOK)
                            predict[orow + col] =
                                (predict[orow + col] + v0 + b2[col]) * m;
                        if (col + 1 < NTOK)
                            predict[orow + col + 1] =
                                (predict[orow + col + 1] + v1 + b2[col + 1]) * m;
                    } else {
                        if (col < NTOK)
                            predict[orow + col]     = (v0 + b2[col]) * m;
                        if (col + 1 < NTOK)
                            predict[orow + col + 1] = (v1 + b2[col + 1]) * m;
                    }
                }
            }
        }
}

// ------------------------- persistent loop kernel ---------------------------
__global__ void __launch_bounds__(256, 2) loop_kernel(
    const float* __restrict__ bhh1, const float* __restrict__ bhh2,
    const float* __restrict__ wa,   const float* __restrict__ ba,
    const float* __restrict__ b2,
    float* __restrict__ alphas, float* __restrict__ predict)
{
    extern __shared__ char dsm[];
    const int cta = blockIdx.x;
    const int tid = threadIdx.x;

    for (int t = 0; t < TT; t++) {
        const bf16*  h2ph = g_h2_h + (size_t)t * B_ * HID_;
        const bf16*  h2pl = g_h2_l + (size_t)t * B_ * HID_;
        const float* h2prev = g_h2all + (size_t)t * B_ * HID_;
        float*       h2next = g_h2all + (size_t)(t + 1) * B_ * HID_;

        // ---- phase 1: stage1 (gih, gh1, gh2), 288 tasks ----
        for (int task = cta; task < 288; task += NCTA) {
            int s = task & 1, x = (task >> 1) % 48, o = task / 96;
            int ko = s * 512;
            if (o == 0)
                gemm_task(h2ph + ko, h2pl + ko, HID_,
                          g_wih1h_h + ko, g_wih1h_l + ko, HID_,
                          g_gih[s], H3, x * 64, 512, nullptr, dsm);
            else if (o == 1)
                gemm_task(g_h1_h + ko, g_h1_l + ko, HID_,
                          g_whh1_h + ko, g_whh1_l + ko, HID_,
                          g_gh1[s], H3, x * 64, 512, s == 0 ? bhh1 : nullptr, dsm);
            else
                gemm_task(h2ph + ko, h2pl + ko, HID_,
                          g_whh2_h + ko, g_whh2_l + ko, HID_,
                          g_gh2[s], H3, x * 64, 512, s == 0 ? bhh2 : nullptr, dsm);
        }
        grid_bar();

        // ---- phase 2: GRU1 pointwise ----
        {
            const float* gip = g_gip + (size_t)t * B_ * H3;
            for (int idx = cta * 256 + tid; idx < B_ * HID_; idx += NCTA * 256) {
                int b = idx >> 10, j = idx & 1023;
                size_t base = (size_t)b * H3 + j;
                float gr = g_giv[base] + gip[base] + g_gih[0][base] + g_gih[1][base];
                float gz = g_giv[base + HID_] + gip[base + HID_]
                         + g_gih[0][base + HID_] + g_gih[1][base + HID_];
                float gn = g_giv[base + 2*HID_] + gip[base + 2*HID_]
                         + g_gih[0][base + 2*HID_] + g_gih[1][base + 2*HID_];
                float ghr = g_gh1[0][base] + g_gh1[1][base];
                float ghz = g_gh1[0][base + HID_] + g_gh1[1][base + HID_];
                float ghn = g_gh1[0][base + 2*HID_] + g_gh1[1][base + 2*HID_];
                float r = 1.f / (1.f + expf(-(gr + ghr)));
                float z = 1.f / (1.f + expf(-(gz + ghz)));
                float n = tanhf(gn + r * ghn);
                float h = (1.f - z) * n + z * g_h1[idx];
                g_h1[idx] = h;
                split2(h, g_h1_h[idx], g_h1_l[idx]);
            }
        }
        grid_bar();

        // ---- phase 3: stage2 (128 tasks) + W2 half-A (157, K 0..511) ----
        if (cta < 128) {
            int task = cta;
            if (task < 32) {
                int s = task & 1, x = (task >> 1);
                int ko = s * 512;
                gemm_task(g_h1_h + ko, g_h1_l + ko, HID_,
                          g_wfq_h + ko, g_wfq_l + ko, HID_,
                          g_qp[s], HID_, x * 64, 512, nullptr, dsm);
            } else {
                int u = task - 32;
                int s = u & 1, x = (u >> 1);
                int ko = s * 512;
                gemm_task(g_h1_h + ko, g_h1_l + ko, HID_,
                          g_wf2h_h + ko, g_wf2h_l + ko, HID_,
                          g_gi2h[s], H3, x * 64, 512, nullptr, dsm);
            }
        } else if (t > 0 && cta - 128 < W2TILES) {
            gemm_task_w2(t - 1, (cta - 128) * 64, 0, 8, 0, b2, predict, dsm);
        }
        grid_bar();

        // ---- phase 4: attention (128) + W2 half-B (157, K 512..1023) ----
        if (cta < B_) {
            int b = cta;
            float* qs  = (float*)dsm;
            float* att = qs + HID_;
            for (int d = tid; d < HID_; d += 256) {
                float qv = g_qp[0][b * HID_ + d] + g_qp[1][b * HID_ + d] + g_bfq[d];
                qs[d] = fmaxf(qv, 0.f) * wa[d];
            }
            __syncthreads();
            int warp = tid >> 5, lane = tid & 31;
            for (int k = warp; k < KOBJ; k += 8) {
                const float* vp = g_vproj + ((size_t)b * KOBJ + k) * HID_;
                float s = 0.f;
                for (int d = lane; d < HID_; d += 32) s += vp[d] * qs[d];
#pragma unroll
                for (int o = 16; o; o >>= 1) s += __shfl_down_sync(0xffffffffu, s, o);
                if (lane == 0) att[k] = s + ba[0];
            }
            __syncthreads();
            if (tid == 0) {
                float mx = att[0];
                for (int k = 1; k < KOBJ; k++) mx = fmaxf(mx, att[k]);
                float ssum = 0.f;
                for (int k = 0; k < KOBJ; k++) { float e = expf(att[k] - mx); att[k] = e; ssum += e; }
                float inv = 1.f / ssum;
                for (int k = 0; k < KOBJ; k++) att[k] *= inv;
            }
            __syncthreads();
            if (tid < KOBJ) {
                float m = (t < g_dl[b]) ? 1.f : 0.f;
                alphas[((size_t)b * MAXLEN + t) * KOBJ + tid] = att[tid] * m;
            }
            for (int d = tid; d < VD; d += 256) {
                const float* vb = g_vs + (size_t)b * KOBJ * VD + d;
                float s = 0.f;
#pragma unroll 6
                for (int k = 0; k < KOBJ; k++) s += att[k] * vb[(size_t)k * VD];
                split2(s, g_attv_h[b * VD + d], g_attv_l[b * VD + d]);
            }
        } else if (t > 0 && cta - 128 < W2TILES) {
            gemm_task_w2(t - 1, (cta - 128) * 64, 512, 8, 1, b2, predict, dsm);
        }
        grid_bar();

        // ---- phase 5: gi2att (192 tasks) ----
        for (int task = cta; task < 192; task += NCTA) {
            int s = task & 3, x = task >> 2;
            int ko = s * 512;
            gemm_task(g_attv_h + ko, g_attv_l + ko, VD,
                      g_wih2v_h + ko, g_wih2v_l + ko, VD,
                      g_p0[s], H3, x * 64, 512, nullptr, dsm);
        }
        grid_bar();

        // ---- phase 6: GRU2 pointwise ----
        {
            bf16* hh = g_h2_h + (size_t)(t + 1) * B_ * HID_;
            bf16* hl = g_h2_l + (size_t)(t + 1) * B_ * HID_;
            for (int idx = cta * 256 + tid; idx < B_ * HID_; idx += NCTA * 256) {
                int b = idx >> 10, j = idx & 1023;
                size_t base = (size_t)b * H3 + j;
                float gr = g_bi2f[j], gz = g_bi2f[j + HID_], gn = g_bi2f[j + 2*HID_];
#pragma unroll
                for (int s = 0; s < 4; s++) {
                    gr += g_p0[s][base]; gz += g_p0[s][base + HID_]; gn += g_p0[s][base + 2*HID_];
                }
#pragma unroll
                for (int s = 0; s < 2; s++) {
                    gr += g_gi2h[s][base]; gz += g_gi2h[s][base + HID_]; gn += g_gi2h[s][base + 2*HID_];
                }
                float ghr = g_gh2[0][base] + g_gh2[1][base];
                float ghz = g_gh2[0][base + HID_] + g_gh2[1][base + HID_];
                float ghn = g_gh2[0][base + 2*HID_] + g_gh2[1][base + 2*HID_];
                float r = 1.f / (1.f + expf(-(gr + ghr)));
                float z = 1.f / (1.f + expf(-(gz + ghz)));
                float n = tanhf(gn + r * ghn);
                float h = (1.f - z) * n + z * h2prev[idx];
                h2next[idx] = h;
                split2(h, hh[idx], hl[idx]);
            }
        }
        grid_bar();
    }

    // ---- post-loop: final timestep's W2 + zero tails ----
    for (int task = cta; task < W2TILES; task += NCTA)
        gemm_task_w2(TT - 1, task * 64, 0, 16, 2, b2, predict, dsm);
    for (int idx = cta * 256 + tid; idx < B_ * NTOK + B_ * KOBJ; idx += NCTA * 256) {
        if (idx < B_ * NTOK) {
            int b = idx / NTOK, n = idx % NTOK;
            predict[((size_t)b * MAXLEN + (MAXLEN - 1)) * NTOK + n] = 0.f;
        } else {
            int r = idx - B_ * NTOK;
            int b = r / KOBJ, k = r % KOBJ;
            alphas[((size_t)b * MAXLEN + (MAXLEN - 1)) * KOBJ + k] = 0.f;
        }
    }
}

// ------------------------------- small kernels -----------------------------
__global__ void meta_kernel(const int* __restrict__ cap_len)
{
    int i = threadIdx.x;
    int ci = cap_len[i];
    int rank = 0;
    for (int j = 0; j < B_; j++) {
        int cj = cap_len[j];
        if (cj > ci || (cj == ci && j < i)) rank++;
    }
    g_order[rank] = i;
    __syncthreads();
    g_dl[i] = cap_len[g_order[i]] - 1;
    __syncthreads();
    int dli = g_dl[i];
    for (int t = 0; t < TT; t++) g_mask[t * B_ + i] = (t < dli) ? 1.f : 0.f;
    if (i == 0) { g_barc = 0; g_barg = 0; }
}

__global__ void zero_init_kernel()
{
    int idx = blockIdx.x * 256 + threadIdx.x;
    if (idx < B_ * HID_) {
        g_h1[idx] = 0.f;    g_h1_h[idx] = __float2bfloat16(0.f); g_h1_l[idx] = __float2bfloat16(0.f);
        g_h2all[idx] = 0.f; g_h2_h[idx] = __float2bfloat16(0.f); g_h2_l[idx] = __float2bfloat16(0.f);
    }
}

__global__ void permute_v_kernel(const float* __restrict__ v)
{
    size_t idx = (size_t)blockIdx.x * 256 + threadIdx.x;
    if (idx >= (size_t)B_ * KOBJ * VD) return;
    int b = (int)(idx / ((size_t)KOBJ * VD));
    size_t rest = idx % ((size_t)KOBJ * VD);
    float x = v[(size_t)g_order[b] * KOBJ * VD + rest];
    g_vs[idx] = x;
    split2(x, g_vs_h[idx], g_vs_l[idx]);
}

__global__ void vmean_kernel()
{
    int idx = blockIdx.x * 256 + threadIdx.x;
    if (idx >= B_ * VD) return;
    int b = idx / VD, d = idx % VD;
    const float* p = g_vs + (size_t)b * KOBJ * VD + d;
    float s = 0.f;
#pragma unroll 6
    for (int k = 0; k < KOBJ; k++) s += p[(size_t)k * VD];
    s *= (1.f / (float)KOBJ);
    g_vmean[idx] = s;
    split2(s, g_vm_h[idx], g_vm_l[idx]);
}

__global__ void build_x1p_kernel(const float* __restrict__ caption)
{
    size_t idx = (size_t)blockIdx.x * 256 + threadIdx.x;
    if (idx >= (size_t)TT * B_ * EMB) return;
    int c = (int)(idx % EMB);
    int r = (int)(idx / EMB);
    int t = r / B_, b = r % B_;
    float val = caption[((size_t)g_order[b] * MAXLEN + t) * EMB + c];
    split2(val, g_x1p_h[idx], g_x1p_l[idx]);
}

// mega-convert: one launch, 10 regions (blockIdx.y selects)
struct CvR {
    const float* src; bf16 *hi, *lo;
    int ld, col0, rows, cols;
};
struct CvP { CvR r[10]; };
__global__ void convall_kernel(CvP p)
{
    const CvR rg = p.r[blockIdx.y];
    size_t total = (size_t)rg.rows * rg.cols;
    for (size_t idx = (size_t)blockIdx.x * 256 + threadIdx.x; idx < total;
         idx += (size_t)gridDim.x * 256) {
        int r = (int)(idx / rg.cols), c = (int)(idx % rg.cols);
        split2(rg.src[(size_t)r * rg.ld + rg.col0 + c], rg.hi[idx], rg.lo[idx]);
    }
}

// standalone converter (for post-precompute Wfq/Wf2h)
__global__ void convw_kernel(const float* __restrict__ src, int ld, int col0,
                             int rows, int cols, bf16* __restrict__ hi,
                             bf16* __restrict__ lo)
{
    size_t idx = (size_t)blockIdx.x * 256 + threadIdx.x;
    if (idx >= (size_t)rows * cols) return;
    int r = (int)(idx / cols), c = (int)(idx % cols);
    split2(src[(size_t)r * ld + col0 + c], hi[idx], lo[idx]);
}

__global__ void tsplit_kernel(const float* __restrict__ src,
                              bf16* __restrict__ hi, bf16* __restrict__ lo)
{
    __shared__ float tile[32][33];
    int bx = blockIdx.x * 32, by = blockIdx.y * 32;
#pragma unroll
    for (int i = 0; i < 32; i += 8)
        tile[threadIdx.y + i][threadIdx.x] =
            src[(size_t)(by + threadIdx.y + i) * HID_ + bx + threadIdx.x];
    __syncthreads();
#pragma unroll
    for (int i = 0; i < 32; i += 8) {
        float vv = tile[threadIdx.x][threadIdx.y + i];
        size_t o = (size_t)(bx + threadIdx.y + i) * HID_ + by + threadIdx.x;
        split2(vv, hi[o], lo[o]);
    }
}

__global__ void fusebias_kernel(const float* __restrict__ Wq,
                                const float* __restrict__ bq,
                                const float* __restrict__ b1,
                                const float* __restrict__ Wih2,
                                const float* __restrict__ bih2)
{
    int idx = blockIdx.x * 256 + threadIdx.x;
    if (idx < HID_) {
        const float* w = Wq + (size_t)idx * HID_;
        float s = 0.f;
        for (int j = 0; j < HID_; j++) s += w[j] * b1[j];
        g_bfq[idx] = s + bq[idx];
    } else if (idx < HID_ + H3) {
        int n = idx - HID_;
        const float* w = Wih2 + (size_t)n * H3 + VD;
        float s = 0.f;
        for (int j = 0; j < HID_; j++) s += w[j] * b1[j];
        g_bi2f[n] = s + bih2[n];
    }
}

// --------------------------------- launch ----------------------------------
static inline TZ mkt(const bf16* Ah, const bf16* Al, int lda,
                     const bf16* Wh, const bf16* Wl, int ldw,
                     float* C, int ldc, int M, int N, int K,
                     const float* bias, int mode)
{
    TZ z; z.Ahi = Ah; z.Alo = Al; z.Whi = Wh; z.Wlo = Wl;
    z.C = C; z.bias = bias; z.lda = lda; z.ldw = ldw; z.ldc = ldc;
    z.M = M; z.N = N; z.K = K; z.mode = mode;
    return z;
}

static inline CvR mkcv(const float* src, int ld, int col0, int rows, int cols,
                       bf16* hi, bf16* lo)
{
    CvR r; r.src = src; r.hi = hi; r.lo = lo;
    r.ld = ld; r.col0 = col0; r.rows = rows; r.cols = cols;
    return r;
}

#define SYMADDR(var, sym) cudaGetSymbolAddress((void**)&var, sym)

extern "C" void kernel_launch(void* const* d_in, const int* in_sizes, int n_in,
                              void* d_out, int out_size)
{
    const float* v       = (const float*)d_in[0];
    const float* caption = (const float*)d_in[1];
    const int*   cap_len = (const int*)  d_in[2];
    const float* Wih1    = (const float*)d_in[3];
    const float* Whh1    = (const float*)d_in[4];
    const float* bih1    = (const float*)d_in[5];
    const float* bhh1    = (const float*)d_in[6];
    const float* Wih2    = (const float*)d_in[7];
    const float* Whh2    = (const float*)d_in[8];
    const float* bih2    = (const float*)d_in[9];
    const float* bhh2    = (const float*)d_in[10];
    const float* Wv      = (const float*)d_in[11];
    const float* bv      = (const float*)d_in[12];
    const float* Wq      = (const float*)d_in[13];
    const float* bq      = (const float*)d_in[14];
    const float* wa      = (const float*)d_in[15];
    const float* ba      = (const float*)d_in[16];
    const float* W1      = (const float*)d_in[17];
    const float* b1      = (const float*)d_in[18];
    const float* W2      = (const float*)d_in[19];
    const float* b2      = (const float*)d_in[20];

    float* out     = (float*)d_out;
    float* predict = out;
    float* alphas  = out + (size_t)B_ * MAXLEN * NTOK;

    float *p_giv, *p_gip, *p_Wfq, *p_Wf2h, *p_vproj;
    SYMADDR(p_giv, g_giv);    SYMADDR(p_gip, g_gip);
    SYMADDR(p_Wfq, g_Wfq);    SYMADDR(p_Wf2h, g_Wf2h);
    SYMADDR(p_vproj, g_vproj);

    bf16 *vs_h, *vs_l, *vm_h, *vm_l, *x1p_h, *x1p_l;
    bf16 *w1h_h, *w1h_l, *w1v_h, *w1v_l, *w1p_h, *w1p_l;
    bf16 *wh1_h, *wh1_l, *wh2_h, *wh2_l;
    bf16 *wv_h, *wv_l, *w2v_h, *w2v_l, *w2x_h, *w2x_l, *ww2_h, *ww2_l;
    bf16 *wq_h, *wq_l, *w1t_h, *w1t_l, *wfq_h, *wfq_l, *wf2_h, *wf2_l;
    SYMADDR(vs_h, g_vs_h);   SYMADDR(vs_l, g_vs_l);
    SYMADDR(vm_h, g_vm_h);   SYMADDR(vm_l, g_vm_l);
    SYMADDR(x1p_h, g_x1p_h); SYMADDR(x1p_l, g_x1p_l);
    SYMADDR(w1h_h, g_wih1h_h); SYMADDR(w1h_l, g_wih1h_l);
    SYMADDR(w1v_h, g_w1v_h);   SYMADDR(w1v_l, g_w1v_l);
    SYMADDR(w1p_h, g_w1p_h);   SYMADDR(w1p_l, g_w1p_l);
    SYMADDR(wh1_h, g_whh1_h);  SYMADDR(wh1_l, g_whh1_l);
    SYMADDR(wh2_h, g_whh2_h);  SYMADDR(wh2_l, g_whh2_l);
    SYMADDR(wv_h, g_wv_h);     SYMADDR(wv_l, g_wv_l);
    SYMADDR(w2v_h, g_wih2v_h); SYMADDR(w2v_l, g_wih2v_l);
    SYMADDR(w2x_h, g_wih2x_h); SYMADDR(w2x_l, g_wih2x_l);
    SYMADDR(ww2_h, g_w2_h);    SYMADDR(ww2_l, g_w2_l);
    SYMADDR(wq_h, g_wq_h);     SYMADDR(wq_l, g_wq_l);
    SYMADDR(w1t_h, g_w1t_h);   SYMADDR(w1t_l, g_w1t_l);
    SYMADDR(wfq_h, g_wfq_h);   SYMADDR(wfq_l, g_wfq_l);
    SYMADDR(wf2_h, g_wf2h_h);  SYMADDR(wf2_l, g_wf2h_l);

    const int LOOPSMEM = 2 * LBUF + 1024;   // 99328 B; 2 CTAs/SM = 194 KB
    cudaFuncSetAttribute(tgemm_k<64>,  cudaFuncAttributeMaxDynamicSharedMemorySize,
                         TGC<64>::SMEM);
    cudaFuncSetAttribute(tgemm_k<128>, cudaFuncAttributeMaxDynamicSharedMemorySize,
                         TGC<128>::SMEM);
    cudaFuncSetAttribute(loop_kernel,  cudaFuncAttributeMaxDynamicSharedMemorySize,
                         LOOPSMEM);

    // ---- setup ----
    meta_kernel<<<1, B_>>>(cap_len);
    zero_init_kernel<<<(B_ * HID_ + 255) / 256, 256>>>();
    {   // one launch: all 10 direct weight conversions
        CvP P{};
        P.r[0] = mkcv(Wih1, HID_ + VD + EMB, 1024, H3,   VD,   w1v_h, w1v_l);
        P.r[1] = mkcv(Wih1, HID_ + VD + EMB, 3072, H3,   EMB,  w1p_h, w1p_l);
        P.r[2] = mkcv(Wih1, HID_ + VD + EMB, 0,    H3,   HID_, w1h_h, w1h_l);
        P.r[3] = mkcv(Whh1, HID_,            0,    H3,   HID_, wh1_h, wh1_l);
        P.r[4] = mkcv(Whh2, HID_,            0,    H3,   HID_, wh2_h, wh2_l);
        P.r[5] = mkcv(Wv,   VD,              0,    HID_, VD,   wv_h,  wv_l);
        P.r[6] = mkcv(Wih2, H3,              0,    H3,   VD,   w2v_h, w2v_l);
        P.r[7] = mkcv(Wih2, H3,              2048, H3,   HID_, w2x_h, w2x_l);
        P.r[8] = mkcv(Wq,   HID_,            0,    HID_, HID_, wq_h,  wq_l);
        P.r[9] = mkcv(W2,   HID_,            0,    NTOK, HID_, ww2_h, ww2_l);
        convall_kernel<<<dim3(1024, 10), 256>>>(P);
    }
    permute_v_kernel<<<(unsigned)(((size_t)B_*KOBJ*VD + 255)/256), 256>>>(v);
    vmean_kernel<<<(B_ * VD + 255) / 256, 256>>>();
    build_x1p_kernel<<<(unsigned)(((size_t)TT*B_*EMB + 255)/256), 256>>>(caption);
    tsplit_kernel<<<dim3(32, 32), dim3(32, 8)>>>(W1, w1t_h, w1t_l);
    {   // giv = v_mean @ Wih1[:,1024:3072].T + bih1   [128 x 3072 x K=2048]
        TP P{}; P.mask = nullptr;
        P.z[0] = mkt(vm_h, vm_l, VD, w1v_h, w1v_l, VD,
                     p_giv, H3, B_, H3, VD, bih1, 0);
        tgemm_k<64><<<dim3(H3/64, 1, 1), TGC<64>::THR, TGC<64>::SMEM>>>(P);
    }
    {   // gip = x1p @ Wih1[:,3072:4096].T   [2432 x 3072 x K=1024]
        TP P{}; P.mask = nullptr;
        P.z[0] = mkt(x1p_h, x1p_l, EMB, w1p_h, w1p_l, EMB,
                     p_gip, H3, TT * B_, H3, EMB, nullptr, 0);
        tgemm_k<128><<<dim3(H3/128, (TT*B_)/128, 1), TGC<128>::THR, TGC<128>::SMEM>>>(P);
    }
    {   // tensor precompute: Wfq = Wq@W1 (via W1T); Wf2h = Wih2x@W1
        TP P{}; P.mask = nullptr;
        P.z[0] = mkt(wq_h,  wq_l,  HID_, w1t_h, w1t_l, HID_,
                     p_Wfq,  HID_, HID_, HID_, HID_, nullptr, 0);
        P.z[1] = mkt(w2x_h, w2x_l, HID_, w1t_h, w1t_l, HID_,
                     p_Wf2h, HID_, H3,   HID_, HID_, nullptr, 0);
        tgemm_k<64><<<dim3(HID_/64, H3/128, 2), TGC<64>::THR, TGC<64>::SMEM>>>(P);
    }
    convw_kernel<<<(HID_*HID_ + 255) / 256, 256>>>(p_Wfq,  HID_, 0, HID_, HID_, wfq_h, wfq_l);
    convw_kernel<<<(H3*HID_ + 255) / 256, 256>>>(p_Wf2h, HID_, 0, H3,   HID_, wf2_h, wf2_l);
    fusebias_kernel<<<(HID_ + H3 + 255) / 256, 256>>>(Wq, bq, b1, Wih2, bih2);
    {   // vproj = relu(v_s @ Wv.T + bv)   [4608 x 1024 x K=2048]
        TP P{}; P.mask = nullptr;
        P.z[0] = mkt(vs_h, vs_l, VD, wv_h, wv_l, VD,
                     p_vproj, HID_, B_ * KOBJ, HID_, VD, bv, 1);
        tgemm_k<128><<<dim3(HID_/128, (B_*KOBJ)/128, 1), TGC<128>::THR, TGC<128>::SMEM>>>(P);
    }

    // ---- persistent decode loop (computes all predict rows + tails) ----
    loop_kernel<<<NCTA, 256, LOOPSMEM>>>(bhh1, bhh2, wa, ba, b2, alphas, predict);
}

// round 16
// speedup vs baseline: 1.2396x; 1.0162x over previous
#include <cuda_runtime.h>
#include <cuda_bf16.h>
#include <math.h>

// ---------------------------------------------------------------------------
// BUTDDecoder: B=128, K=36, V_DIM=2048, EMBED=1024, HID=1024, NTOKEN=10000,
// MAX_LEN=20 (T=19 decode steps).
//
// Round 16: gip (prev-embedding gate input) pipelined into the loop like W2:
// phase 5's idle CTAs compute gip[t+1] as 2 K-512 partial slices; host gip
// GEMM shrinks to t=0 only (z-batched with giv). Post-precompute converts
// merged into one launch.
// ---------------------------------------------------------------------------

#define B_     128
#define KOBJ   36
#define VD     2048
#define EMB    1024
#define HID_   1024
#define NTOK   10000
#define MAXLEN 20
#define TT     19
#define H3     3072
#define NCTA   296
#define W2TILES 157          // ceil(10000/64)

typedef unsigned long long ull;
typedef __nv_bfloat16 bf16;

// ------------------------- scratch (device globals) ------------------------
__device__ float g_vs[B_ * KOBJ * VD];
__device__ float g_vmean[B_ * VD];
__device__ float g_vproj[B_ * KOBJ * HID_];
__device__ float g_giv[B_ * H3];
__device__ float g_gipA[B_ * H3], g_gipB[B_ * H3];
__device__ float g_h1[B_ * HID_];
__device__ float g_h2all[(TT + 1) * B_ * HID_];
__device__ float g_gih[2][B_ * H3];
__device__ float g_gh1[2][B_ * H3];
__device__ float g_gh2[2][B_ * H3];
__device__ float g_qp[2][B_ * HID_];
__device__ float g_gi2h[2][B_ * H3];
__device__ float g_p0[4][B_ * H3];
__device__ float g_Wfq[HID_ * HID_];
__device__ float g_Wf2h[H3 * HID_];
__device__ float g_bfq[HID_];
__device__ float g_bi2f[H3];
__device__ int   g_order[B_];
__device__ int   g_dl[B_];
__device__ float g_mask[TT * B_];
__device__ int          g_barc;
__device__ volatile int g_barg;

// bf16 hi/lo operand arrays (activations)
__device__ bf16 g_vs_h[B_ * KOBJ * VD],        g_vs_l[B_ * KOBJ * VD];
__device__ bf16 g_vm_h[B_ * VD],               g_vm_l[B_ * VD];
__device__ bf16 g_x1p_h[TT * B_ * EMB],        g_x1p_l[TT * B_ * EMB];
__device__ bf16 g_h1_h[B_ * HID_],             g_h1_l[B_ * HID_];
__device__ bf16 g_h2_h[(TT + 1) * B_ * HID_],  g_h2_l[(TT + 1) * B_ * HID_];
__device__ bf16 g_attv_h[B_ * VD],             g_attv_l[B_ * VD];

// bf16 hi/lo weight arrays
__device__ bf16 g_wih1h_h[H3 * HID_],  g_wih1h_l[H3 * HID_];   // Wih1[:, :1024]
__device__ bf16 g_w1v_h[H3 * VD],      g_w1v_l[H3 * VD];       // Wih1[:, 1024:3072]
__device__ bf16 g_w1p_h[H3 * EMB],     g_w1p_l[H3 * EMB];      // Wih1[:, 3072:4096]
__device__ bf16 g_whh1_h[H3 * HID_],   g_whh1_l[H3 * HID_];
__device__ bf16 g_whh2_h[H3 * HID_],   g_whh2_l[H3 * HID_];
__device__ bf16 g_wv_h[HID_ * VD],     g_wv_l[HID_ * VD];
__device__ bf16 g_wih2v_h[H3 * VD],    g_wih2v_l[H3 * VD];     // Wih2[:, :2048]
__device__ bf16 g_wih2x_h[H3 * HID_],  g_wih2x_l[H3 * HID_];   // Wih2[:, 2048:]
__device__ bf16 g_w2_h[NTOK * HID_],   g_w2_l[NTOK * HID_];
__device__ bf16 g_wq_h[HID_ * HID_],   g_wq_l[HID_ * HID_];
__device__ bf16 g_w1t_h[HID_ * HID_],  g_w1t_l[HID_ * HID_];
__device__ bf16 g_wfq_h[HID_ * HID_],  g_wfq_l[HID_ * HID_];
__device__ bf16 g_wf2h_h[H3 * HID_],   g_wf2h_l[H3 * HID_];

// --------------------------- small helpers ---------------------------------
__device__ __forceinline__ void split2(float x, bf16& h, bf16& l) {
    h = __float2bfloat16(x);
    l = __float2bfloat16(x - __bfloat162float(h));
}
__device__ __forceinline__ unsigned smem_u32(const void* p) {
    return (unsigned)__cvta_generic_to_shared(p);
}
__device__ __forceinline__ void cpa16(unsigned dst, const void* src, int sz) {
    asm volatile("cp.async.ca.shared.global [%0], [%1], 16, %2;"
                 :: "r"(dst), "l"(src), "r"(sz));
}

#define LDM_X4(r0, r1, r2, r3, addr) \
    asm volatile("ldmatrix.sync.aligned.m8n8.x4.shared.b16 {%0,%1,%2,%3}, [%4];" \
        : "=r"(r0), "=r"(r1), "=r"(r2), "=r"(r3) : "r"(addr))

#define MMA16816(c, a, b) \
    asm volatile("mma.sync.aligned.m16n8k16.row.col.f32.bf16.bf16.f32 " \
        "{%0,%1,%2,%3}, {%4,%5,%6,%7}, {%8,%9}, {%0,%1,%2,%3};" \
        : "+f"((c)[0]), "+f"((c)[1]), "+f"((c)[2]), "+f"((c)[3]) \
        : "r"((a)[0]), "r"((a)[1]), "r"((a)[2]), "r"((a)[3]), \
          "r"((b)[0]), "r"((b)[1]))

// ----------------- host-launched tensor GEMM (big GEMMs) -------------------
struct TZ {
    const bf16 *Ahi, *Alo, *Whi, *Wlo;
    float* C; const float* bias;
    int lda, ldw, ldc, M, N, K, mode;
};
struct TP { TZ z[3]; const float* mask; };

template<int BN> struct TGC {
    static constexpr int BUF   = 32768 + BN * 256;
    static constexpr int SMEM  = 2 * BUF + 1024;
    static constexpr int THR   = BN * 2;
    static constexpr int WN    = BN / 32;
    static constexpr int RPI   = BN / 4;
    static constexpr int AIT   = 128 / RPI;
};

template<int BN>
__global__ void __launch_bounds__(TGC<BN>::THR) tgemm_k(TP p)
{
    const TZ gz = p.z[blockIdx.z];
    const int bn0 = blockIdx.x * BN;  if (bn0 >= gz.N) return;
    const int bm0 = blockIdx.y * 128; if (bm0 >= gz.M) return;
    const int tid = threadIdx.x, wid = tid >> 5, lane = tid & 31;
    const int wm = wid / TGC<BN>::WN, wn = wid % TGC<BN>::WN;

    extern __shared__ char dsm[];
    unsigned dbase = smem_u32(dsm);
    unsigned s0 = (dbase + 1023u) & ~1023u;
    unsigned sAh[2], sAl[2], sBh[2], sBl[2];
#pragma unroll
    for (int b = 0; b < 2; b++) {
        sAh[b] = s0 + b * TGC<BN>::BUF;
        sAl[b] = sAh[b] + 16384;
        sBh[b] = sAl[b] + 16384;
        sBl[b] = sBh[b] + BN * 128;
    }

    const int lrow = tid >> 3;
    const int lch  = tid & 7;
    auto load_chunk = [&](int c, int buf) {
        const int c0 = c * 64;
#pragma unroll
        for (int i = 0; i < TGC<BN>::AIT; i++) {
            int row = i * TGC<BN>::RPI + lrow;
            unsigned off = (unsigned)(row * 128) + (unsigned)(((lch ^ (row & 7)) * 16));
            cpa16(sAh[buf] + off, gz.Ahi + (size_t)(bm0 + row) * gz.lda + c0 + lch * 8, 16);
            cpa16(sAl[buf] + off, gz.Alo + (size_t)(bm0 + row) * gz.lda + c0 + lch * 8, 16);
        }
#pragma unroll
        for (int i = 0; i < 4; i++) {
            int row = i * TGC<BN>::RPI + lrow;
            unsigned off = (unsigned)(row * 128) + (unsigned)(((lch ^ (row & 7)) * 16));
            int n = bn0 + row;
            int sz = (n < gz.N) ? 16 : 0;
            int nn = (n < gz.N) ? n : 0;
            cpa16(sBh[buf] + off, gz.Whi + (size_t)nn * gz.ldw + c0 + lch * 8, sz);
            cpa16(sBl[buf] + off, gz.Wlo + (size_t)nn * gz.ldw + c0 + lch * 8, sz);
        }
        asm volatile("cp.async.commit_group;");
    };

    float acc[4][4][4];
#pragma unroll
    for (int mi = 0; mi < 4; mi++)
#pragma unroll
        for (int nj = 0; nj < 4; nj++)
#pragma unroll
            for (int e = 0; e < 4; e++) acc[mi][nj][e] = 0.f;

    const int xorkey = lane & 7;
    const int nch = gz.K / 64;
    load_chunk(0, 0);

    for (int c = 0; c < nch; c++) {
        if (c + 1 < nch) {
            load_chunk(c + 1, (c + 1) & 1);
            asm volatile("cp.async.wait_group 1;");
        } else {
            asm volatile("cp.async.wait_group 0;");
        }
        __syncthreads();
        const unsigned tAh = sAh[c & 1], tAl = sAl[c & 1];
        const unsigned tBh = sBh[c & 1], tBl = sBl[c & 1];
#pragma unroll
        for (int ks = 0; ks < 4; ks++) {
            unsigned Ah[4][4], Al[4][4];
            {
                const int arow = wm * 64 + (lane & 15);
                const unsigned aoff =
                    (unsigned)((((2 * ks) + (lane >> 4)) ^ xorkey) * 16);
#pragma unroll
                for (int mi = 0; mi < 4; mi++) {
                    unsigned ad = (unsigned)((arow + mi * 16) * 128) + aoff;
                    LDM_X4(Ah[mi][0], Ah[mi][1], Ah[mi][2], Ah[mi][3], tAh + ad);
                    LDM_X4(Al[mi][0], Al[mi][1], Al[mi][2], Al[mi][3], tAl + ad);
                }
            }
            unsigned Bh[4][2], Bl[4][2];
            {
                const int brow = wn * 32 + (lane & 7) + ((lane >> 4) << 3);
                const unsigned boff =
                    (unsigned)((((2 * ks) + ((lane >> 3) & 1)) ^ xorkey) * 16);
                unsigned r0, r1, r2, r3;
                unsigned b0 = (unsigned)(brow * 128) + boff;
                LDM_X4(r0, r1, r2, r3, tBh + b0);
                Bh[0][0] = r0; Bh[0][1] = r1; Bh[1][0] = r2; Bh[1][1] = r3;
                LDM_X4(r0, r1, r2, r3, tBh + b0 + 16 * 128);
                Bh[2][0] = r0; Bh[2][1] = r1; Bh[3][0] = r2; Bh[3][1] = r3;
                LDM_X4(r0, r1, r2, r3, tBl + b0);
                Bl[0][0] = r0; Bl[0][1] = r1; Bl[1][0] = r2; Bl[1][1] = r3;
                LDM_X4(r0, r1, r2, r3, tBl + b0 + 16 * 128);
                Bl[2][0] = r0; Bl[2][1] = r1; Bl[3][0] = r2; Bl[3][1] = r3;
            }
#pragma unroll
            for (int mi = 0; mi < 4; mi++)
#pragma unroll
                for (int nj = 0; nj < 4; nj++) {
                    MMA16816(acc[mi][nj], Ah[mi], Bh[nj]);
                    MMA16816(acc[mi][nj], Ah[mi], Bl[nj]);
                    MMA16816(acc[mi][nj], Al[mi], Bh[nj]);
                }
        }
        __syncthreads();
    }

    const int g = lane >> 2, tig = lane & 3;
    auto stc = [&](int m, int n, float val) {
        if (n >= gz.N) return;
        if (gz.bias) val += gz.bias[n];
        if (gz.mode == 1) val = fmaxf(val, 0.f);
        gz.C[(size_t)m * gz.ldc + n] = val;
    };
#pragma unroll
    for (int mi = 0; mi < 4; mi++)
#pragma unroll
        for (int nj = 0; nj < 4; nj++) {
            int row = bm0 + wm * 64 + mi * 16 + g;
            int col = bn0 + wn * 32 + nj * 8 + 2 * tig;
            stc(row,     col,     acc[mi][nj][0]);
            stc(row,     col + 1, acc[mi][nj][1]);
            stc(row + 8, col,     acc[mi][nj][2]);
            stc(row + 8, col + 1, acc[mi][nj][3]);
        }
}

// ------------------ persistent-loop device machinery ------------------------
__device__ __forceinline__ void grid_bar()
{
    __syncthreads();
    if (threadIdx.x == 0) {
        int gen = g_barg;
        __threadfence();
        if (atomicAdd(&g_barc, 1) == NCTA - 1) {
            g_barc = 0;
            __threadfence();
            g_barg = gen + 1;
        } else {
            while (g_barg == gen) __nanosleep(32);
            __threadfence();
        }
    }
    __syncthreads();
}

#define LBUF 49152   // per-stage smem inside the loop (Ah16K|Al16K|Bh8K|Bl8K)

// one 128x64xK GEMM tile, 256 threads (8 warps: 4m x 2n), double-buffered.
__device__ __noinline__ void gemm_task(
    const bf16* __restrict__ Ah0, const bf16* __restrict__ Al0, int lda,
    const bf16* __restrict__ Wh0, const bf16* __restrict__ Wl0, int ldw,
    float* __restrict__ C, int ldc, int bn0, int Ksz,
    const float* __restrict__ bias, char* dsm)
{
    const int tid = threadIdx.x, wid = tid >> 5, lane = tid & 31;
    const int wm = wid >> 1, wn = wid & 1;

    unsigned dbase = smem_u32(dsm);
    unsigned s0 = (dbase + 1023u) & ~1023u;
    unsigned sAh[2], sAl[2], sBh[2], sBl[2];
#pragma unroll
    for (int b = 0; b < 2; b++) {
        sAh[b] = s0 + b * LBUF;
        sAl[b] = sAh[b] + 16384;
        sBh[b] = sAl[b] + 16384;
        sBl[b] = sBh[b] + 8192;
    }

    const int lrow = tid >> 3;
    const int lch  = tid & 7;
    const bf16* Wb_h = Wh0 + (size_t)bn0 * ldw;
    const bf16* Wb_l = Wl0 + (size_t)bn0 * ldw;
    auto load_chunk = [&](int c, int buf) {
        const int c0 = c * 64;
#pragma unroll
        for (int i = 0; i < 4; i++) {
            int row = i * 32 + lrow;
            unsigned off = (unsigned)(row * 128) + (unsigned)(((lch ^ (row & 7)) * 16));
            cpa16(sAh[buf] + off, Ah0 + (size_t)row * lda + c0 + lch * 8, 16);
            cpa16(sAl[buf] + off, Al0 + (size_t)row * lda + c0 + lch * 8, 16);
        }
#pragma unroll
        for (int i = 0; i < 2; i++) {
            int row = i * 32 + lrow;
            unsigned off = (unsigned)(row * 128) + (unsigned)(((lch ^ (row & 7)) * 16));
            cpa16(sBh[buf] + off, Wb_h + (size_t)row * ldw + c0 + lch * 8, 16);
            cpa16(sBl[buf] + off, Wb_l + (size_t)row * ldw + c0 + lch * 8, 16);
        }
        asm volatile("cp.async.commit_group;");
    };

    float acc[2][4][4];
#pragma unroll
    for (int mi = 0; mi < 2; mi++)
#pragma unroll
        for (int nj = 0; nj < 4; nj++)
#pragma unroll
            for (int e = 0; e < 4; e++) acc[mi][nj][e] = 0.f;

    const int xorkey = lane & 7;
    const int nch = Ksz / 64;
    load_chunk(0, 0);

    for (int c = 0; c < nch; c++) {
        if (c + 1 < nch) {
            load_chunk(c + 1, (c + 1) & 1);
            asm volatile("cp.async.wait_group 1;");
        } else {
            asm volatile("cp.async.wait_group 0;");
        }
        __syncthreads();
        const unsigned tAh = sAh[c & 1], tAl = sAl[c & 1];
        const unsigned tBh = sBh[c & 1], tBl = sBl[c & 1];

#pragma unroll
        for (int ks = 0; ks < 4; ks++) {
            unsigned Ahf[2][4], Alf[2][4];
            {
                const int arow = wm * 32 + (lane & 15);
                const unsigned aoff =
                    (unsigned)((((2 * ks) + (lane >> 4)) ^ xorkey) * 16);
#pragma unroll
                for (int mi = 0; mi < 2; mi++) {
                    unsigned ad = (unsigned)((arow + mi * 16) * 128) + aoff;
                    LDM_X4(Ahf[mi][0], Ahf[mi][1], Ahf[mi][2], Ahf[mi][3], tAh + ad);
                    LDM_X4(Alf[mi][0], Alf[mi][1], Alf[mi][2], Alf[mi][3], tAl + ad);
                }
            }
            unsigned Bh[4][2], Bl[4][2];
            {
                const int brow = wn * 32 + (lane & 7) + ((lane >> 4) << 3);
                const unsigned boff =
                    (unsigned)((((2 * ks) + ((lane >> 3) & 1)) ^ xorkey) * 16);
                unsigned r0, r1, r2, r3;
                unsigned b0 = (unsigned)(brow * 128) + boff;
                LDM_X4(r0, r1, r2, r3, tBh + b0);
                Bh[0][0] = r0; Bh[0][1] = r1; Bh[1][0] = r2; Bh[1][1] = r3;
                LDM_X4(r0, r1, r2, r3, tBh + b0 + 16 * 128);
                Bh[2][0] = r0; Bh[2][1] = r1; Bh[3][0] = r2; Bh[3][1] = r3;
                LDM_X4(r0, r1, r2, r3, tBl + b0);
                Bl[0][0] = r0; Bl[0][1] = r1; Bl[1][0] = r2; Bl[1][1] = r3;
                LDM_X4(r0, r1, r2, r3, tBl + b0 + 16 * 128);
                Bl[2][0] = r0; Bl[2][1] = r1; Bl[3][0] = r2; Bl[3][1] = r3;
            }
#pragma unroll
            for (int mi = 0; mi < 2; mi++)
#pragma unroll
                for (int nj = 0; nj < 4; nj++) {
                    MMA16816(acc[mi][nj], Ahf[mi], Bh[nj]);
                    MMA16816(acc[mi][nj], Ahf[mi], Bl[nj]);
                    MMA16816(acc[mi][nj], Alf[mi], Bh[nj]);
                }
        }
        __syncthreads();
    }

    const int g = lane >> 2, tig = lane & 3;
#pragma unroll
    for (int mi = 0; mi < 2; mi++)
#pragma unroll
        for (int nj = 0; nj < 4; nj++) {
            int row = wm * 32 + mi * 16 + g;
            int col = bn0 + wn * 32 + nj * 8 + 2 * tig;
            float v0 = acc[mi][nj][0], v1 = acc[mi][nj][1];
            float v2 = acc[mi][nj][2], v3 = acc[mi][nj][3];
            if (bias) {
                v0 += bias[col]; v1 += bias[col + 1];
                v2 += bias[col]; v3 += bias[col + 1];
            }
            C[(size_t)row * ldc + col]           = v0;
            C[(size_t)row * ldc + col + 1]       = v1;
            C[(size_t)(row + 8) * ldc + col]     = v2;
            C[(size_t)(row + 8) * ldc + col + 1] = v3;
        }
}

// W2 tile for timestep ts, cols [bn0, bn0+64), K slice [kbase, kbase+64*nch).
// mode 0: raw partial; mode 1: += then bias+mask; mode 2: full single pass.
__device__ __noinline__ void gemm_task_w2(
    int ts, int bn0, int kbase, int nch, int mode,
    const float* __restrict__ b2, float* __restrict__ predict, char* dsm)
{
    const bf16* Ah0 = g_h2_h + (size_t)(ts + 1) * B_ * HID_ + kbase;
    const bf16* Al0 = g_h2_l + (size_t)(ts + 1) * B_ * HID_ + kbase;
    const int tid = threadIdx.x, wid = tid >> 5, lane = tid & 31;
    const int wm = wid >> 1, wn = wid & 1;

    unsigned dbase = smem_u32(dsm);
    unsigned s0 = (dbase + 1023u) & ~1023u;
    unsigned sAh[2], sAl[2], sBh[2], sBl[2];
#pragma unroll
    for (int b = 0; b < 2; b++) {
        sAh[b] = s0 + b * LBUF;
        sAl[b] = sAh[b] + 16384;
        sBh[b] = sAl[b] + 16384;
        sBl[b] = sBh[b] + 8192;
    }

    const int lrow = tid >> 3;
    const int lch  = tid & 7;
    auto load_chunk = [&](int c, int buf) {
        const int c0 = c * 64;
#pragma unroll
        for (int i = 0; i < 4; i++) {
            int row = i * 32 + lrow;
            unsigned off = (unsigned)(row * 128) + (unsigned)(((lch ^ (row & 7)) * 16));
            cpa16(sAh[buf] + off, Ah0 + (size_t)row * HID_ + c0 + lch * 8, 16);
            cpa16(sAl[buf] + off, Al0 + (size_t)row * HID_ + c0 + lch * 8, 16);
        }
#pragma unroll
        for (int i = 0; i < 2; i++) {
            int row = i * 32 + lrow;
            unsigned off = (unsigned)(row * 128) + (unsigned)(((lch ^ (row & 7)) * 16));
            int n = bn0 + row;
            int sz = (n < NTOK) ? 16 : 0;
            int nn = (n < NTOK) ? n : 0;
            cpa16(sBh[buf] + off, g_w2_h + (size_t)nn * HID_ + kbase + c0 + lch * 8, sz);
            cpa16(sBl[buf] + off, g_w2_l + (size_t)nn * HID_ + kbase + c0 + lch * 8, sz);
        }
        asm volatile("cp.async.commit_group;");
    };

    float acc[2][4][4];
#pragma unroll
    for (int mi = 0; mi < 2; mi++)
#pragma unroll
        for (int nj = 0; nj < 4; nj++)
#pragma unroll
            for (int e = 0; e < 4; e++) acc[mi][nj][e] = 0.f;

    const int xorkey = lane & 7;
    load_chunk(0, 0);

    for (int c = 0; c < nch; c++) {
        if (c + 1 < nch) {
            load_chunk(c + 1, (c + 1) & 1);
            asm volatile("cp.async.wait_group 1;");
        } else {
            asm volatile("cp.async.wait_group 0;");
        }
        __syncthreads();
        const unsigned tAh = sAh[c & 1], tAl = sAl[c & 1];
        const unsigned tBh = sBh[c & 1], tBl = sBl[c & 1];

#pragma unroll
        for (int ks = 0; ks < 4; ks++) {
            unsigned Ahf[2][4], Alf[2][4];
            {
                const int arow = wm * 32 + (lane & 15);
                const unsigned aoff =
                    (unsigned)((((2 * ks) + (lane >> 4)) ^ xorkey) * 16);
#pragma unroll
                for (int mi = 0; mi < 2; mi++) {
                    unsigned ad = (unsigned)((arow + mi * 16) * 128) + aoff;
                    LDM_X4(Ahf[mi][0], Ahf[mi][1], Ahf[mi][2], Ahf[mi][3], tAh + ad);
                    LDM_X4(Alf[mi][0], Alf[mi][1], Alf[mi][2], Alf[mi][3], tAl + ad);
                }
            }
            unsigned Bh[4][2], Bl[4][2];
            {
                const int brow = wn * 32 + (lane & 7) + ((lane >> 4) << 3);
                const unsigned boff =
                    (unsigned)((((2 * ks) + ((lane >> 3) & 1)) ^ xorkey) * 16);
                unsigned r0, r1, r2, r3;
                unsigned b0 = (unsigned)(brow * 128) + boff;
                LDM_X4(r0, r1, r2, r3, tBh + b0);
                Bh[0][0] = r0; Bh[0][1] = r1; Bh[1][0] = r2; Bh[1][1] = r3;
                LDM_X4(r0, r1, r2, r3, tBh + b0 + 16 * 128);
                Bh[2][0] = r0; Bh[2][1] = r1; Bh[3][0] = r2; Bh[3][1] = r3;
                LDM_X4(r0, r1, r2, r3, tBl + b0);
                Bl[0][0] = r0; Bl[0][1] = r1; Bl[1][0] = r2; Bl[1][1] = r3;
                LDM_X4(r0, r1, r2, r3, tBl + b0 + 16 * 128);
                Bl[2][0] = r0; Bl[2][1] = r1; Bl[3][0] = r2; Bl[3][1] = r3;
            }
#pragma unroll
            for (int mi = 0; mi < 2; mi++)
#pragma unroll
                for (int nj = 0; nj < 4; nj++) {
                    MMA16816(acc[mi][nj], Ahf[mi], Bh[nj]);
                    MMA16816(acc[mi][nj], Ahf[mi], Bl[nj]);
                    MMA16816(acc[mi][nj], Alf[mi], Bh[nj]);
                }
        }
        __syncthreads();
    }

    const int g = lane >> 2, tig = lane & 3;
#pragma unroll
    for (int mi = 0; mi < 2; mi++)
#pragma unroll
        for (int nj = 0; nj < 4; nj++) {
            int b0r = wm * 32 + mi * 16 + g;
            int col = bn0 + wn * 32 + nj * 8 + 2 * tig;
#pragma unroll
            for (int half = 0; half < 2; half++) {
                int b = b0r + half * 8;
                size_t orow = ((size_t)b * MAXLEN + ts) * NTOK;
                float v0 = acc[mi][nj][half * 2 + 0];
                float v1 = acc[mi][nj][half * 2 + 1];
                if (mode == 0) {
                    if (col < NTOK)     predict[orow + col]     = v0;
                    if (col + 1 < NTOK) predict[orow + col + 1] = v1;
                } else {
                    float m = g_mask[ts * B_ + b];
                    if (mode == 1) {
                        if (col < NTOK)
                            predict[orow + col] =
                                (predict[orow + col] + v0 + b2[col]) * m;
                        if (col + 1 < NTOK)
                            predict[orow + col + 1] =
                                (predict[orow + col + 1] + v1 + b2[col + 1]) * m;
                    } else {
                        if (col < NTOK)
                            predict[orow + col]     = (v0 + b2[col]) * m;
                        if (col + 1 < NTOK)
                            predict[orow + col + 1] = (v1 + b2[col + 1]) * m;
                    }
                }
            }
        }
}

// ------------------------- persistent loop kernel ---------------------------
__global__ void __launch_bounds__(256, 2) loop_kernel(
    const float* __restrict__ bhh1, const float* __restrict__ bhh2,
    const float* __restrict__ wa,   const float* __restrict__ ba,
    const float* __restrict__ b2,
    float* __restrict__ alphas, float* __restrict__ predict)
{
    extern __shared__ char dsm[];
    const int cta = blockIdx.x;
    const int tid = threadIdx.x;

    for (int t = 0; t < TT; t++) {
        const bf16*  h2ph = g_h2_h + (size_t)t * B_ * HID_;
        const bf16*  h2pl = g_h2_l + (size_t)t * B_ * HID_;
        const float* h2prev = g_h2all + (size_t)t * B_ * HID_;
        float*       h2next = g_h2all + (size_t)(t + 1) * B_ * HID_;

        // ---- phase 1: stage1 (gih, gh1, gh2), 288 tasks ----
        for (int task = cta; task < 288; task += NCTA) {
            int s = task & 1, x = (task >> 1) % 48, o = task / 96;
            int ko = s * 512;
            if (o == 0)
                gemm_task(h2ph + ko, h2pl + ko, HID_,
                          g_wih1h_h + ko, g_wih1h_l + ko, HID_,
                          g_gih[s], H3, x * 64, 512, nullptr, dsm);
            else if (o == 1)
                gemm_task(g_h1_h + ko, g_h1_l + ko, HID_,
                          g_whh1_h + ko, g_whh1_l + ko, HID_,
                          g_gh1[s], H3, x * 64, 512, s == 0 ? bhh1 : nullptr, dsm);
            else
                gemm_task(h2ph + ko, h2pl + ko, HID_,
                          g_whh2_h + ko, g_whh2_l + ko, HID_,
                          g_gh2[s], H3, x * 64, 512, s == 0 ? bhh2 : nullptr, dsm);
        }
        grid_bar();

        // ---- phase 2: GRU1 pointwise (gi = giv + gipA + gipB + gih) ----
        {
            for (int idx = cta * 256 + tid; idx < B_ * HID_; idx += NCTA * 256) {
                int b = idx >> 10, j = idx & 1023;
                size_t base = (size_t)b * H3 + j;
                float gr = g_giv[base] + g_gipA[base] + g_gipB[base]
                         + g_gih[0][base] + g_gih[1][base];
                float gz = g_giv[base + HID_] + g_gipA[base + HID_] + g_gipB[base + HID_]
                         + g_gih[0][base + HID_] + g_gih[1][base + HID_];
                float gn = g_giv[base + 2*HID_] + g_gipA[base + 2*HID_] + g_gipB[base + 2*HID_]
                         + g_gih[0][base + 2*HID_] + g_gih[1][base + 2*HID_];
                float ghr = g_gh1[0][base] + g_gh1[1][base];
                float ghz = g_gh1[0][base + HID_] + g_gh1[1][base + HID_];
                float ghn = g_gh1[0][base + 2*HID_] + g_gh1[1][base + 2*HID_];
                float r = 1.f / (1.f + expf(-(gr + ghr)));
                float z = 1.f / (1.f + expf(-(gz + ghz)));
                float n = tanhf(gn + r * ghn);
                float h = (1.f - z) * n + z * g_h1[idx];
                g_h1[idx] = h;
                split2(h, g_h1_h[idx], g_h1_l[idx]);
            }
        }
        grid_bar();

        // ---- phase 3: stage2 (128 tasks) + W2 half-A (157, K 0..511) ----
        if (cta < 128) {
            int task = cta;
            if (task < 32) {
                int s = task & 1, x = (task >> 1);
                int ko = s * 512;
                gemm_task(g_h1_h + ko, g_h1_l + ko, HID_,
                          g_wfq_h + ko, g_wfq_l + ko, HID_,
                          g_qp[s], HID_, x * 64, 512, nullptr, dsm);
            } else {
                int u = task - 32;
                int s = u & 1, x = (u >> 1);
                int ko = s * 512;
                gemm_task(g_h1_h + ko, g_h1_l + ko, HID_,
                          g_wf2h_h + ko, g_wf2h_l + ko, HID_,
                          g_gi2h[s], H3, x * 64, 512, nullptr, dsm);
            }
        } else if (t > 0 && cta - 128 < W2TILES) {
            gemm_task_w2(t - 1, (cta - 128) * 64, 0, 8, 0, b2, predict, dsm);
        }
        grid_bar();

        // ---- phase 4: attention (128) + W2 half-B (157, K 512..1023) ----
        if (cta < B_) {
            int b = cta;
            float* qs  = (float*)dsm;
            float* att = qs + HID_;
            for (int d = tid; d < HID_; d += 256) {
                float qv = g_qp[0][b * HID_ + d] + g_qp[1][b * HID_ + d] + g_bfq[d];
                qs[d] = fmaxf(qv, 0.f) * wa[d];
            }
            __syncthreads();
            int warp = tid >> 5, lane = tid & 31;
            for (int k = warp; k < KOBJ; k += 8) {
                const float* vp = g_vproj + ((size_t)b * KOBJ + k) * HID_;
                float s = 0.f;
                for (int d = lane; d < HID_; d += 32) s += vp[d] * qs[d];
#pragma unroll
                for (int o = 16; o; o >>= 1) s += __shfl_down_sync(0xffffffffu, s, o);
                if (lane == 0) att[k] = s + ba[0];
            }
            __syncthreads();
            if (tid == 0) {
                float mx = att[0];
                for (int k = 1; k < KOBJ; k++) mx = fmaxf(mx, att[k]);
                float ssum = 0.f;
                for (int k = 0; k < KOBJ; k++) { float e = expf(att[k] - mx); att[k] = e; ssum += e; }
                float inv = 1.f / ssum;
                for (int k = 0; k < KOBJ; k++) att[k] *= inv;
            }
            __syncthreads();
            if (tid < KOBJ) {
                float m = (t < g_dl[b]) ? 1.f : 0.f;
                alphas[((size_t)b * MAXLEN + t) * KOBJ + tid] = att[tid] * m;
            }
            for (int d = tid; d < VD; d += 256) {
                const float* vb = g_vs + (size_t)b * KOBJ * VD + d;
                float s = 0.f;
#pragma unroll 6
                for (int k = 0; k < KOBJ; k++) s += att[k] * vb[(size_t)k * VD];
                split2(s, g_attv_h[b * VD + d], g_attv_l[b * VD + d]);
            }
        } else if (t > 0 && cta - 128 < W2TILES) {
            gemm_task_w2(t - 1, (cta - 128) * 64, 512, 8, 1, b2, predict, dsm);
        }
        grid_bar();

        // ---- phase 5: gi2att (192 tasks) + gip[t+1] (96 tasks) ----
        if (cta < 192) {
            int task = cta;
            int s = task & 3, x = task >> 2;
            int ko = s * 512;
            gemm_task(g_attv_h + ko, g_attv_l + ko, VD,
                      g_wih2v_h + ko, g_wih2v_l + ko, VD,
                      g_p0[s], H3, x * 64, 512, nullptr, dsm);
        } else if (t + 1 < TT && cta - 192 < 96) {
            int u = cta - 192;
            int s = u & 1, x = u >> 1;
            int ko = s * 512;
            gemm_task(g_x1p_h + (size_t)(t + 1) * B_ * EMB + ko,
                      g_x1p_l + (size_t)(t + 1) * B_ * EMB + ko, EMB,
                      g_w1p_h + ko, g_w1p_l + ko, EMB,
                      s ? g_gipB : g_gipA, H3, x * 64, 512, nullptr, dsm);
        }
        grid_bar();

        // ---- phase 6: GRU2 pointwise ----
        {
            bf16* hh = g_h2_h + (size_t)(t + 1) * B_ * HID_;
            bf16* hl = g_h2_l + (size_t)(t + 1) * B_ * HID_;
            for (int idx = cta * 256 + tid; idx < B_ * HID_; idx += NCTA * 256) {
                int b = idx >> 10, j = idx & 1023;
                size_t base = (size_t)b * H3 + j;
                float gr = g_bi2f[j], gz = g_bi2f[j + HID_], gn = g_bi2f[j + 2*HID_];
#pragma unroll
                for (int s = 0; s < 4; s++) {
                    gr += g_p0[s][base]; gz += g_p0[s][base + HID_]; gn += g_p0[s][base + 2*HID_];
                }
#pragma unroll
                for (int s = 0; s < 2; s++) {
                    gr += g_gi2h[s][base]; gz += g_gi2h[s][base + HID_]; gn += g_gi2h[s][base + 2*HID_];
                }
                float ghr = g_gh2[0][base] + g_gh2[1][base];
                float ghz = g_gh2[0][base + HID_] + g_gh2[1][base + HID_];
                float ghn = g_gh2[0][base + 2*HID_] + g_gh2[1][base + 2*HID_];
                float r = 1.f / (1.f + expf(-(gr + ghr)));
                float z = 1.f / (1.f + expf(-(gz + ghz)));
                float n = tanhf(gn + r * ghn);
                float h = (1.f - z) * n + z * h2prev[idx];
                h2next[idx] = h;
                split2(h, hh[idx], hl[idx]);
            }
        }
        grid_bar();
    }

    // ---- post-loop: final timestep's W2 + zero tails ----
    for (int task = cta; task < W2TILES; task += NCTA)
        gemm_task_w2(TT - 1, task * 64, 0, 16, 2, b2, predict, dsm);
    for (int idx = cta * 256 + tid; idx < B_ * NTOK + B_ * KOBJ; idx += NCTA * 256) {
        if (idx < B_ * NTOK) {
            int b = idx / NTOK, n = idx % NTOK;
            predict[((size_t)b * MAXLEN + (MAXLEN - 1)) * NTOK + n] = 0.f;
        } else {
            int r = idx - B_ * NTOK;
            int b = r / KOBJ, k = r % KOBJ;
            alphas[((size_t)b * MAXLEN + (MAXLEN - 1)) * KOBJ + k] = 0.f;
        }
    }
}

// ------------------------------- small kernels -----------------------------
__global__ void meta_kernel(const int* __restrict__ cap_len)
{
    int i = threadIdx.x;
    int ci = cap_len[i];
    int rank = 0;
    for (int j = 0; j < B_; j++) {
        int cj = cap_len[j];
        if (cj > ci || (cj == ci && j < i)) rank++;
    }
    g_order[rank] = i;
    __syncthreads();
    g_dl[i] = cap_len[g_order[i]] - 1;
    __syncthreads();
    int dli = g_dl[i];
    for (int t = 0; t < TT; t++) g_mask[t * B_ + i] = (t < dli) ? 1.f : 0.f;
    if (i == 0) { g_barc = 0; g_barg = 0; }
}

__global__ void zero_init_kernel()
{
    int idx = blockIdx.x * 256 + threadIdx.x;
    if (idx < B_ * HID_) {
        g_h1[idx] = 0.f;    g_h1_h[idx] = __float2bfloat16(0.f); g_h1_l[idx] = __float2bfloat16(0.f);
        g_h2all[idx] = 0.f; g_h2_h[idx] = __float2bfloat16(0.f); g_h2_l[idx] = __float2bfloat16(0.f);
    }
}

__global__ void permute_v_kernel(const float* __restrict__ v)
{
    size_t idx = (size_t)blockIdx.x * 256 + threadIdx.x;
    if (idx >= (size_t)B_ * KOBJ * VD) return;
    int b = (int)(idx / ((size_t)KOBJ * VD));
    size_t rest = idx % ((size_t)KOBJ * VD);
    float x = v[(size_t)g_order[b] * KOBJ * VD + rest];
    g_vs[idx] = x;
    split2(x, g_vs_h[idx], g_vs_l[idx]);
}

__global__ void vmean_kernel()
{
    int idx = blockIdx.x * 256 + threadIdx.x;
    if (idx >= B_ * VD) return;
    int b = idx / VD, d = idx % VD;
    const float* p = g_vs + (size_t)b * KOBJ * VD + d;
    float s = 0.f;
#pragma unroll 6
    for (int k = 0; k < KOBJ; k++) s += p[(size_t)k * VD];
    s *= (1.f / (float)KOBJ);
    g_vmean[idx] = s;
    split2(s, g_vm_h[idx], g_vm_l[idx]);
}

__global__ void build_x1p_kernel(const float* __restrict__ caption)
{
    size_t idx = (size_t)blockIdx.x * 256 + threadIdx.x;
    if (idx >= (size_t)TT * B_ * EMB) return;
    int c = (int)(idx % EMB);
    int r = (int)(idx / EMB);
    int t = r / B_, b = r % B_;
    float val = caption[((size_t)g_order[b] * MAXLEN + t) * EMB + c];
    split2(val, g_x1p_h[idx], g_x1p_l[idx]);
}

// mega-convert: one launch, up to 10 regions (blockIdx.y selects)
struct CvR {
    const float* src; bf16 *hi, *lo;
    int ld, col0, rows, cols;
};
struct CvP { CvR r[10]; };
__global__ void convall_kernel(CvP p)
{
    const CvR rg = p.r[blockIdx.y];
    size_t total = (size_t)rg.rows * rg.cols;
    for (size_t idx = (size_t)blockIdx.x * 256 + threadIdx.x; idx < total;
         idx += (size_t)gridDim.x * 256) {
        int r = (int)(idx / rg.cols), c = (int)(idx % rg.cols);
        split2(rg.src[(size_t)r * rg.ld + rg.col0 + c], rg.hi[idx], rg.lo[idx]);
    }
}

__global__ void tsplit_kernel(const float* __restrict__ src,
                              bf16* __restrict__ hi, bf16* __restrict__ lo)
{
    __shared__ float tile[32][33];
    int bx = blockIdx.x * 32, by = blockIdx.y * 32;
#pragma unroll
    for (int i = 0; i < 32; i += 8)
        tile[threadIdx.y + i][threadIdx.x] =
            src[(size_t)(by + threadIdx.y + i) * HID_ + bx + threadIdx.x];
    __syncthreads();
#pragma unroll
    for (int i = 0; i < 32; i += 8) {
        float vv = tile[threadIdx.x][threadIdx.y + i];
        size_t o = (size_t)(bx + threadIdx.y + i) * HID_ + by + threadIdx.x;
        split2(vv, hi[o], lo[o]);
    }
}

__global__ void fusebias_kernel(const float* __restrict__ Wq,
                                const float* __restrict__ bq,
                                const float* __restrict__ b1,
                                const float* __restrict__ Wih2,
                                const float* __restrict__ bih2)
{
    int idx = blockIdx.x * 256 + threadIdx.x;
    if (idx < HID_) {
        const float* w = Wq + (size_t)idx * HID_;
        float s = 0.f;
        for (int j = 0; j < HID_; j++) s += w[j] * b1[j];
        g_bfq[idx] = s + bq[idx];
    } else if (idx < HID_ + H3) {
        int n = idx - HID_;
        const float* w = Wih2 + (size_t)n * H3 + VD;
        float s = 0.f;
        for (int j = 0; j < HID_; j++) s += w[j] * b1[j];
        g_bi2f[n] = s + bih2[n];
    }
}

// --------------------------------- launch ----------------------------------
static inline TZ mkt(const bf16* Ah, const bf16* Al, int lda,
                     const bf16* Wh, const bf16* Wl, int ldw,
                     float* C, int ldc, int M, int N, int K,
                     const float* bias, int mode)
{
    TZ z; z.Ahi = Ah; z.Alo = Al; z.Whi = Wh; z.Wlo = Wl;
    z.C = C; z.bias = bias; z.lda = lda; z.ldw = ldw; z.ldc = ldc;
    z.M = M; z.N = N; z.K = K; z.mode = mode;
    return z;
}

static inline CvR mkcv(const float* src, int ld, int col0, int rows, int cols,
                       bf16* hi, bf16* lo)
{
    CvR r; r.src = src; r.hi = hi; r.lo = lo;
    r.ld = ld; r.col0 = col0; r.rows = rows; r.cols = cols;
    return r;
}

#define SYMADDR(var, sym) cudaGetSymbolAddress((void**)&var, sym)

extern "C" void kernel_launch(void* const* d_in, const int* in_sizes, int n_in,
                              void* d_out, int out_size)
{
    const float* v       = (const float*)d_in[0];
    const float* caption = (const float*)d_in[1];
    const int*   cap_len = (const int*)  d_in[2];
    const float* Wih1    = (const float*)d_in[3];
    const float* Whh1    = (const float*)d_in[4];
    const float* bih1    = (const float*)d_in[5];
    const float* bhh1    = (const float*)d_in[6];
    const float* Wih2    = (const float*)d_in[7];
    const float* Whh2    = (const float*)d_in[8];
    const float* bih2    = (const float*)d_in[9];
    const float* bhh2    = (const float*)d_in[10];
    const float* Wv      = (const float*)d_in[11];
    const float* bv      = (const float*)d_in[12];
    const float* Wq      = (const float*)d_in[13];
    const float* bq      = (const float*)d_in[14];
    const float* wa      = (const float*)d_in[15];
    const float* ba      = (const float*)d_in[16];
    const float* W1      = (const float*)d_in[17];
    const float* b1      = (const float*)d_in[18];
    const float* W2      = (const float*)d_in[19];
    const float* b2      = (const float*)d_in[20];

    float* out     = (float*)d_out;
    float* predict = out;
    float* alphas  = out + (size_t)B_ * MAXLEN * NTOK;

    float *p_giv, *p_gipA, *p_gipB, *p_Wfq, *p_Wf2h, *p_vproj;
    SYMADDR(p_giv, g_giv);    SYMADDR(p_gipA, g_gipA);  SYMADDR(p_gipB, g_gipB);
    SYMADDR(p_Wfq, g_Wfq);    SYMADDR(p_Wf2h, g_Wf2h);
    SYMADDR(p_vproj, g_vproj);

    bf16 *vs_h, *vs_l, *vm_h, *vm_l, *x1p_h, *x1p_l;
    bf16 *w1h_h, *w1h_l, *w1v_h, *w1v_l, *w1p_h, *w1p_l;
    bf16 *wh1_h, *wh1_l, *wh2_h, *wh2_l;
    bf16 *wv_h, *wv_l, *w2v_h, *w2v_l, *w2x_h, *w2x_l, *ww2_h, *ww2_l;
    bf16 *wq_h, *wq_l, *w1t_h, *w1t_l, *wfq_h, *wfq_l, *wf2_h, *wf2_l;
    SYMADDR(vs_h, g_vs_h);   SYMADDR(vs_l, g_vs_l);
    SYMADDR(vm_h, g_vm_h);   SYMADDR(vm_l, g_vm_l);
    SYMADDR(x1p_h, g_x1p_h); SYMADDR(x1p_l, g_x1p_l);
    SYMADDR(w1h_h, g_wih1h_h); SYMADDR(w1h_l, g_wih1h_l);
    SYMADDR(w1v_h, g_w1v_h);   SYMADDR(w1v_l, g_w1v_l);
    SYMADDR(w1p_h, g_w1p_h);   SYMADDR(w1p_l, g_w1p_l);
    SYMADDR(wh1_h, g_whh1_h);  SYMADDR(wh1_l, g_whh1_l);
    SYMADDR(wh2_h, g_whh2_h);  SYMADDR(wh2_l, g_whh2_l);
    SYMADDR(wv_h, g_wv_h);     SYMADDR(wv_l, g_wv_l);
    SYMADDR(w2v_h, g_wih2v_h); SYMADDR(w2v_l, g_wih2v_l);
    SYMADDR(w2x_h, g_wih2x_h); SYMADDR(w2x_l, g_wih2x_l);
    SYMADDR(ww2_h, g_w2_h);    SYMADDR(ww2_l, g_w2_l);
    SYMADDR(wq_h, g_wq_h);     SYMADDR(wq_l, g_wq_l);
    SYMADDR(w1t_h, g_w1t_h);   SYMADDR(w1t_l, g_w1t_l);
    SYMADDR(wfq_h, g_wfq_h);   SYMADDR(wfq_l, g_wfq_l);
    SYMADDR(wf2_h, g_wf2h_h);  SYMADDR(wf2_l, g_wf2h_l);

    const int LOOPSMEM = 2 * LBUF + 1024;   // 99328 B; 2 CTAs/SM
    cudaFuncSetAttribute(tgemm_k<64>,  cudaFuncAttributeMaxDynamicSharedMemorySize,
                         TGC<64>::SMEM);
    cudaFuncSetAttribute(tgemm_k<128>, cudaFuncAttributeMaxDynamicSharedMemorySize,
                         TGC<128>::SMEM);
    cudaFuncSetAttribute(loop_kernel,  cudaFuncAttributeMaxDynamicSharedMemorySize,
                         LOOPSMEM);

    // ---- setup ----
    meta_kernel<<<1, B_>>>(cap_len);
    zero_init_kernel<<<(B_ * HID_ + 255) / 256, 256>>>();
    {   // one launch: all 10 direct weight conversions
        CvP P{};
        P.r[0] = mkcv(Wih1, HID_ + VD + EMB, 1024, H3,   VD,   w1v_h, w1v_l);
        P.r[1] = mkcv(Wih1, HID_ + VD + EMB, 3072, H3,   EMB,  w1p_h, w1p_l);
        P.r[2] = mkcv(Wih1, HID_ + VD + EMB, 0,    H3,   HID_, w1h_h, w1h_l);
        P.r[3] = mkcv(Whh1, HID_,            0,    H3,   HID_, wh1_h, wh1_l);
        P.r[4] = mkcv(Whh2, HID_,            0,    H3,   HID_, wh2_h, wh2_l);
        P.r[5] = mkcv(Wv,   VD,              0,    HID_, VD,   wv_h,  wv_l);
        P.r[6] = mkcv(Wih2, H3,              0,    H3,   VD,   w2v_h, w2v_l);
        P.r[7] = mkcv(Wih2, H3,              2048, H3,   HID_, w2x_h, w2x_l);
        P.r[8] = mkcv(Wq,   HID_,            0,    HID_, HID_, wq_h,  wq_l);
        P.r[9] = mkcv(W2,   HID_,            0,    NTOK, HID_, ww2_h, ww2_l);
        convall_kernel<<<dim3(1024, 10), 256>>>(P);
    }
    permute_v_kernel<<<(unsigned)(((size_t)B_*KOBJ*VD + 255)/256), 256>>>(v);
    vmean_kernel<<<(B_ * VD + 255) / 256, 256>>>();
    build_x1p_kernel<<<(unsigned)(((size_t)TT*B_*EMB + 255)/256), 256>>>(caption);
    tsplit_kernel<<<dim3(32, 32), dim3(32, 8)>>>(W1, w1t_h, w1t_l);
    {   // giv (+bih1) and gip t=0 halves, z-batched (M=128 each)
        TP P{}; P.mask = nullptr;
        P.z[0] = mkt(vm_h, vm_l, VD, w1v_h, w1v_l, VD,
                     p_giv, H3, B_, H3, VD, bih1, 0);
        P.z[1] = mkt(x1p_h, x1p_l, EMB, w1p_h, w1p_l, EMB,
                     p_gipA, H3, B_, H3, 512, nullptr, 0);
        P.z[2] = mkt(x1p_h + 512, x1p_l + 512, EMB, w1p_h + 512, w1p_l + 512, EMB,
                     p_gipB, H3, B_, H3, 512, nullptr, 0);
        tgemm_k<64><<<dim3(H3/64, 1, 3), TGC<64>::THR, TGC<64>::SMEM>>>(P);
    }
    {   // tensor precompute: Wfq = Wq@W1 (via W1T); Wf2h = Wih2x@W1
        TP P{}; P.mask = nullptr;
        P.z[0] = mkt(wq_h,  wq_l,  HID_, w1t_h, w1t_l, HID_,
                     p_Wfq,  HID_, HID_, HID_, HID_, nullptr, 0);
        P.z[1] = mkt(w2x_h, w2x_l, HID_, w1t_h, w1t_l, HID_,
                     p_Wf2h, HID_, H3,   HID_, HID_, nullptr, 0);
        tgemm_k<64><<<dim3(HID_/64, H3/128, 2), TGC<64>::THR, TGC<64>::SMEM>>>(P);
    }
    {   // one launch: Wfq + Wf2h bf16 conversion
        CvP P{};
        P.r[0] = mkcv(p_Wfq,  HID_, 0, HID_, HID_, wfq_h, wfq_l);
        P.r[1] = mkcv(p_Wf2h, HID_, 0, H3,   HID_, wf2_h, wf2_l);
        convall_kernel<<<dim3(512, 2), 256>>>(P);
    }
    fusebias_kernel<<<(HID_ + H3 + 255) / 256, 256>>>(Wq, bq, b1, Wih2, bih2);
    {   // vproj = relu(v_s @ Wv.T + bv)   [4608 x 1024 x K=2048]
        TP P{}; P.mask = nullptr;
        P.z[0] = mkt(vs_h, vs_l, VD, wv_h, wv_l, VD,
                     p_vproj, HID_, B_ * KOBJ, HID_, VD, bv, 1);
        tgemm_k<128><<<dim3(HID_/128, (B_*KOBJ)/128, 1), TGC<128>::THR, TGC<128>::SMEM>>>(P);
    }

    // ---- persistent decode loop (predict rows, gip pipeline, tails) ----
    loop_kernel<<<NCTA, 256, LOOPSMEM>>>(bhh1, bhh2, wa, ba, b2, alphas, predict);
}